// round 12
// baseline (speedup 1.0000x reference)
#include <cuda_runtime.h>
#include <math.h>

// ---------------- problem constants ----------------
#define BB 64
#define TT 32
#define HH 512
#define MM 256
#define WWD 64
#define RR 4
#define IFACE 471
#define G4H 2048
#define NNOUT 768
#define CLIPV 20.0f
#define DELTA 1e-6f
#define PXZ (BB*480)

// ---------------- device state ----------------
__device__ float g_xprojp[BB*TT*G4H];   // permuted x-projection incl. biases, [b*T+t][4h+g]
__device__ float g_px[2*BB*480];        // split-K partials for xi
__device__ float g_h0buf[2*BB*HH];      // parity buffers for h0
__device__ float g_in1[2*BB*1024];      // parity buffers for [h0 | h1]
__device__ float g_c0[BB*HH];
__device__ float g_c1[BB*HH];
__device__ float g_outb[BB*HH];
__device__ float g_mem[BB*MM*WWD];
__device__ float g_link[BB*MM*MM];
__device__ float g_prec[BB*MM];
__device__ float g_rw[BB*RR*MM];
__device__ float g_ww[BB*MM];
__device__ float g_usage[BB*MM];
__device__ float g_ys[BB*TT*NNOUT];
__device__ float g_W0p[G4H*512];        // permuted Whh0  (row n'=4h+g)
__device__ float g_Wih0p[G4H*256];      // permuted Wih0[:, :256]
__device__ float g_W1p[G4H*1024];       // permuted [Wih1 | Whh1]
__device__ float g_bp0[G4H];
__device__ float g_bp1[G4H];

// ---------------- fast-math helpers ----------------
__device__ __forceinline__ float sigf(float x) {
    return __fdividef(1.f, 1.f + __expf(-x));
}
__device__ __forceinline__ float tanhfast(float x) {
    float e = __expf(-2.f * fabsf(x));
    float r = __fdividef(1.f - e, 1.f + e);
    return copysignf(r, x);
}
__device__ __forceinline__ float splusf(float x) {
    return fmaxf(x, 0.f) + log1pf(__expf(-fabsf(x)));
}

// ---------------- generic C = A * B^T (B row-major [N][K]) ----------------
// Software-pipelined: next k-tile prefetched into registers before compute.
#define TKC 16
__global__ void __launch_bounds__(256) gemm_bt(
                        const float* __restrict__ A, int lda,
                        const float* __restrict__ Bw, int ldb,
                        float* __restrict__ C, int ldc, long zstride,
                        int N, int Klen,
                        const float* __restrict__ bias0,
                        int tanhA)
{
    __shared__ float As[TKC][68];
    __shared__ __align__(16) float Bs[TKC][34];

    const int tid = threadIdx.x;
    const int tx = tid & 15;
    const int ty = tid >> 4;
    const int row0 = blockIdx.y * 64;
    const int n0 = blockIdx.x * 32;
    const int kstart = blockIdx.z * Klen;
    C += (long)blockIdx.z * zstride;

    float acc[4][2] = {};

    const int la_m = tid >> 2;
    const int la_k = (tid & 3) * 4;
    const int lb_n = tid >> 3;
    const int lb_k = (tid & 7) * 2;

    const float* Ab = A + (long)(row0 + la_m) * lda + kstart + la_k;
    const bool bvalid = (n0 + lb_n) < N;
    const float* Bb = Bw + (long)(n0 + lb_n) * ldb + kstart + lb_k;

    float a0 = Ab[0], a1 = Ab[1], a2 = Ab[2], a3 = Ab[3];
    float b0 = 0.f, b1 = 0.f;
    if (bvalid) { b0 = Bb[0]; b1 = Bb[1]; }

    for (int k0 = 0; k0 < Klen; k0 += TKC) {
        float sa0 = a0, sa1 = a1, sa2 = a2, sa3 = a3;
        if (tanhA) { sa0 = tanhfast(sa0); sa1 = tanhfast(sa1);
                     sa2 = tanhfast(sa2); sa3 = tanhfast(sa3); }
        __syncthreads();
        As[la_k + 0][la_m] = sa0; As[la_k + 1][la_m] = sa1;
        As[la_k + 2][la_m] = sa2; As[la_k + 3][la_m] = sa3;
        Bs[lb_k][lb_n] = b0; Bs[lb_k + 1][lb_n] = b1;
        __syncthreads();
        if (k0 + TKC < Klen) {
            a0 = Ab[k0 + TKC + 0]; a1 = Ab[k0 + TKC + 1];
            a2 = Ab[k0 + TKC + 2]; a3 = Ab[k0 + TKC + 3];
            if (bvalid) { b0 = Bb[k0 + TKC]; b1 = Bb[k0 + TKC + 1]; }
        }
        #pragma unroll
        for (int kk = 0; kk < TKC; kk++) {
            float4 av = *(const float4*)&As[kk][ty * 4];
            float2 bv = *(const float2*)&Bs[kk][tx * 2];
            acc[0][0] += av.x * bv.x; acc[0][1] += av.x * bv.y;
            acc[1][0] += av.y * bv.x; acc[1][1] += av.y * bv.y;
            acc[2][0] += av.z * bv.x; acc[2][1] += av.z * bv.y;
            acc[3][0] += av.w * bv.x; acc[3][1] += av.w * bv.y;
        }
    }
    #pragma unroll
    for (int i = 0; i < 4; i++) {
        int m = row0 + ty * 4 + i;
        #pragma unroll
        for (int j = 0; j < 2; j++) {
            int n = n0 + tx * 2 + j;
            if (n < N) {
                float v = acc[i][j];
                if (bias0) v += bias0[n];
                C[(long)m * ldc + n] = v;
            }
        }
    }
}

// ---------------- init: permute weights + init state ----------------
__global__ void __launch_bounds__(256) init_kernel(
                            const float* __restrict__ h0in,
                            const float* __restrict__ Wih0,
                            const float* __restrict__ Whh0,
                            const float* __restrict__ bih0,
                            const float* __restrict__ bhh0,
                            const float* __restrict__ Wih1,
                            const float* __restrict__ Whh1,
                            const float* __restrict__ bih1,
                            const float* __restrict__ bhh1)
{
    int i = blockIdx.x * 256 + threadIdx.x;
    if (i < BB * MM * MM) g_link[i] = 0.f;
    if (i < BB * MM * WWD) g_mem[i] = DELTA;
    if (i < G4H * 1024) {
        int n = i >> 10, k = i & 1023;
        int h = n >> 2, g = n & 3;
        g_W1p[i] = (k < 512) ? Wih1[(g * 512 + h) * 512 + k]
                             : Whh1[(g * 512 + h) * 512 + (k - 512)];
    }
    if (i < G4H * 512) {
        int n = i >> 9, k = i & 511;
        int h = n >> 2, g = n & 3;
        g_W0p[i] = Whh0[(g * 512 + h) * 512 + k];
    }
    if (i < G4H * 256) {
        int n = i >> 8, k = i & 255;
        int h = n >> 2, g = n & 3;
        g_Wih0p[i] = Wih0[(g * 512 + h) * 512 + k];
    }
    if (i < G4H) {
        int h = i >> 2, g = i & 3;
        g_bp0[i] = bih0[g * 512 + h] + bhh0[g * 512 + h];
        g_bp1[i] = bih1[g * 512 + h] + bhh1[g * 512 + h];
    }
    if (i < BB * HH) {
        g_h0buf[i] = h0in[i];
        g_c0[i] = h0in[i];
        g_c1[i] = h0in[32768 + i];
    }
    if (i < BB * 1024) {
        int b = i >> 10, c = i & 1023;
        if (c >= 512) g_in1[i] = h0in[32768 + b * 512 + (c - 512)];
    }
    if (i < BB * RR * MM) g_rw[i] = DELTA;
    if (i < BB * MM) { g_ww[i] = DELTA; g_usage[i] = 0.f; g_prec[i] = 0.f; }
}

// ---------------- fused GEMM + LSTM cells: in-block split-K, 512 threads ----
// Block = 64 batch x 16 gate-cols (4 h). Group g = tid>>8 computes half of K
// into its own smem tile; partials combined via smem; group 0 runs the fused
// cell epilogue. Epilogue operands prefetched before the mainloop.
__global__ void __launch_bounds__(512) lstm0_kernel(
                             int t, const float* __restrict__ A,
                             float* __restrict__ h0next, float* __restrict__ in1cur)
{
    __shared__ float As[2][32][65];
    __shared__ __align__(16) float Bs[2][32][20];
    __shared__ float s_part[4][256];
    const int tid = threadIdx.x;
    const int g = tid >> 8, gtid = tid & 255;
    const int r = gtid & 63, q = gtid >> 6;
    const int n0 = blockIdx.x * 16;
    const int a_row = gtid >> 2, a_kb = (gtid & 3) * 8;
    const int b_n = gtid >> 4, b_k2 = (gtid & 15) * 2;
    const float* Ap = A + a_row * 512 + g * 256 + a_kb;
    const float* Bp = g_W0p + (n0 + b_n) * 512 + g * 256 + b_k2;
    float acc0 = 0.f, acc1 = 0.f, acc2 = 0.f, acc3 = 0.f;

    const int h = blockIdx.x * 4 + q;
    float4 xp = make_float4(0.f, 0.f, 0.f, 0.f);
    float cold = 0.f;
    if (g == 0) {
        xp = *(const float4*)&g_xprojp[((long)(r * TT + t)) * G4H + h * 4];
        cold = g_c0[r * 512 + h];
    }

    float4 ra0 = *(const float4*)(Ap);
    float4 ra1 = *(const float4*)(Ap + 4);
    float rb0 = Bp[0], rb1 = Bp[1];

    #pragma unroll 1
    for (int k0 = 0; k0 < 256; k0 += 32) {
        __syncthreads();
        As[g][a_kb + 0][a_row] = ra0.x; As[g][a_kb + 1][a_row] = ra0.y;
        As[g][a_kb + 2][a_row] = ra0.z; As[g][a_kb + 3][a_row] = ra0.w;
        As[g][a_kb + 4][a_row] = ra1.x; As[g][a_kb + 5][a_row] = ra1.y;
        As[g][a_kb + 6][a_row] = ra1.z; As[g][a_kb + 7][a_row] = ra1.w;
        Bs[g][b_k2][b_n] = rb0; Bs[g][b_k2 + 1][b_n] = rb1;
        __syncthreads();
        if (k0 + 32 < 256) {
            ra0 = *(const float4*)(Ap + k0 + 32);
            ra1 = *(const float4*)(Ap + k0 + 36);
            rb0 = Bp[k0 + 32]; rb1 = Bp[k0 + 33];
        }
        #pragma unroll
        for (int kk = 0; kk < 32; kk++) {
            float a = As[g][kk][r];
            float4 b4 = *(const float4*)&Bs[g][kk][q * 4];
            acc0 += a * b4.x; acc1 += a * b4.y; acc2 += a * b4.z; acc3 += a * b4.w;
        }
    }
    if (g == 1) {
        s_part[0][gtid] = acc0; s_part[1][gtid] = acc1;
        s_part[2][gtid] = acc2; s_part[3][gtid] = acc3;
    }
    __syncthreads();
    if (g == 0) {
        acc0 += s_part[0][gtid]; acc1 += s_part[1][gtid];
        acc2 += s_part[2][gtid]; acc3 += s_part[3][gtid];
        float gi = acc0 + xp.x, gf = acc1 + xp.y, gg = acc2 + xp.z, go = acc3 + xp.w;
        float c = sigf(gf) * cold + sigf(gi) * tanhfast(gg);
        g_c0[r * 512 + h] = c;
        float hh = sigf(go) * tanhfast(c);
        h0next[r * 512 + h] = hh;
        in1cur[r * 1024 + h] = hh;
    }
}

__global__ void __launch_bounds__(512) lstm1_kernel(
                             int t, const float* __restrict__ A,
                             float* __restrict__ in1next)
{
    __shared__ float As[2][32][65];
    __shared__ __align__(16) float Bs[2][32][20];
    __shared__ float s_part[4][256];
    const int tid = threadIdx.x;
    const int g = tid >> 8, gtid = tid & 255;
    const int r = gtid & 63, q = gtid >> 6;
    const int n0 = blockIdx.x * 16;
    const int a_row = gtid >> 2, a_kb = (gtid & 3) * 8;
    const int b_n = gtid >> 4, b_k2 = (gtid & 15) * 2;
    const float* Ap = A + a_row * 1024 + g * 512 + a_kb;
    const float* Bp = g_W1p + (n0 + b_n) * 1024 + g * 512 + b_k2;
    float acc0 = 0.f, acc1 = 0.f, acc2 = 0.f, acc3 = 0.f;

    const int h = blockIdx.x * 4 + q;
    float4 bi = make_float4(0.f, 0.f, 0.f, 0.f);
    float cold = 0.f;
    if (g == 0) {
        bi = *(const float4*)&g_bp1[h * 4];
        cold = g_c1[r * 512 + h];
    }

    float4 ra0 = *(const float4*)(Ap);
    float4 ra1 = *(const float4*)(Ap + 4);
    float rb0 = Bp[0], rb1 = Bp[1];

    #pragma unroll 1
    for (int k0 = 0; k0 < 512; k0 += 32) {
        __syncthreads();
        As[g][a_kb + 0][a_row] = ra0.x; As[g][a_kb + 1][a_row] = ra0.y;
        As[g][a_kb + 2][a_row] = ra0.z; As[g][a_kb + 3][a_row] = ra0.w;
        As[g][a_kb + 4][a_row] = ra1.x; As[g][a_kb + 5][a_row] = ra1.y;
        As[g][a_kb + 6][a_row] = ra1.z; As[g][a_kb + 7][a_row] = ra1.w;
        Bs[g][b_k2][b_n] = rb0; Bs[g][b_k2 + 1][b_n] = rb1;
        __syncthreads();
        if (k0 + 32 < 512) {
            ra0 = *(const float4*)(Ap + k0 + 32);
            ra1 = *(const float4*)(Ap + k0 + 36);
            rb0 = Bp[k0 + 32]; rb1 = Bp[k0 + 33];
        }
        #pragma unroll
        for (int kk = 0; kk < 32; kk++) {
            float a = As[g][kk][r];
            float4 b4 = *(const float4*)&Bs[g][kk][q * 4];
            acc0 += a * b4.x; acc1 += a * b4.y; acc2 += a * b4.z; acc3 += a * b4.w;
        }
    }
    if (g == 1) {
        s_part[0][gtid] = acc0; s_part[1][gtid] = acc1;
        s_part[2][gtid] = acc2; s_part[3][gtid] = acc3;
    }
    __syncthreads();
    if (g == 0) {
        acc0 += s_part[0][gtid]; acc1 += s_part[1][gtid];
        acc2 += s_part[2][gtid]; acc3 += s_part[3][gtid];
        float gi = acc0 + bi.x, gf = acc1 + bi.y, gg = acc2 + bi.z, go = acc3 + bi.w;
        float c = sigf(gf) * cold + sigf(gi) * tanhfast(gg);
        g_c1[r * 512 + h] = c;
        float h1 = sigf(go) * tanhfast(c);
        in1next[r * 1024 + 512 + h] = h1;
        float o = fminf(fmaxf(h1, -CLIPV), CLIPV);
        g_outb[r * 512 + h] = o;
        g_ys[((long)(r * TT + t)) * NNOUT + h] = o;
    }
}

// ---------------- memory step: one block (512 thr) per batch ----------------
#define MEM_SMEM_FLOATS (256*65 + 4*1024 + 6*256 + 256 + 480 + 512 + 16 + 96)

__device__ __forceinline__ float red512_max(float v, float* s_scr, int tid) {
    #pragma unroll
    for (int o = 16; o > 0; o >>= 1) v = fmaxf(v, __shfl_xor_sync(0xffffffffu, v, o));
    if ((tid & 31) == 0) s_scr[tid >> 5] = v;
    __syncthreads();
    if (tid < 32) {
        float x = (tid < 16) ? s_scr[tid] : -1e30f;
        #pragma unroll
        for (int o = 8; o > 0; o >>= 1) x = fmaxf(x, __shfl_xor_sync(0xffffffffu, x, o));
        if (tid == 0) s_scr[0] = x;
    }
    __syncthreads();
    float rr = s_scr[0];
    __syncthreads();
    return rr;
}
__device__ __forceinline__ float red512_sum(float v, float* s_scr, int tid) {
    #pragma unroll
    for (int o = 16; o > 0; o >>= 1) v += __shfl_xor_sync(0xffffffffu, v, o);
    if ((tid & 31) == 0) s_scr[tid >> 5] = v;
    __syncthreads();
    if (tid < 32) {
        float x = (tid < 16) ? s_scr[tid] : 0.f;
        #pragma unroll
        for (int o = 8; o > 0; o >>= 1) x += __shfl_xor_sync(0xffffffffu, x, o);
        if (tid == 0) s_scr[0] = x;
    }
    __syncthreads();
    float rr = s_scr[0];
    __syncthreads();
    return rr;
}

__global__ void __launch_bounds__(512) mem_kernel(int t, const float* __restrict__ bif)
{
    extern __shared__ float sm[];
    float* s_mem  = sm;                     // 256*65
    float* s_rwo  = s_mem + 256 * 65;       // 1024
    float* s_rwn  = s_rwo + 1024;           // 1024
    float* s_fwd  = s_rwn + 1024;           // 1024
    float* s_bwd  = s_fwd + 1024;           // 1024
    float* s_ww   = s_bwd + 1024;           // 256
    float* s_wwo  = s_ww + 256;
    float* s_prec = s_wwo + 256;
    float* s_alloc= s_prec + 256;
    float* s_wcw  = s_alloc + 256;
    float* s_key  = s_wcw + 256;
    int*   s_idx  = (int*)(s_key + 256);    // 256
    float* s_xi   = (float*)(s_idx + 256);  // 480
    float* s_red  = s_xi + 480;             // 512
    float* s_rm   = s_red + 512;            // 16
    float* s_scr  = s_rm + 16;              // 96

    const int tid = threadIdx.x;
    const int b = blockIdx.x;
    const int m = tid & 255;
    const int warp = tid >> 5, lane = tid & 31;

    // ---- loads + xi activations ----
    for (int i = tid; i < IFACE; i += 512) {
        float v = bif[i] + g_px[b * 480 + i] + g_px[PXZ + b * 480 + i];
        if      (i < 256) v = tanhfast(v);
        else if (i < 260) v = splusf(v);
        else if (i < 324) v = tanhfast(v);
        else if (i == 324) v = splusf(v);
        else if (i < 389) v = sigf(v);
        else if (i < 453) v = tanhfast(v);
        else if (i < 459) v = sigf(v);
        s_xi[i] = v;
    }
    for (int i = tid; i < 1024; i += 512) s_rwo[i] = g_rw[b * 1024 + i];
    if (tid < 256) {
        s_wwo[tid]  = g_ww[b * 256 + tid];
        s_prec[tid] = g_prec[b * 256 + tid];
    }
    for (int i = tid; i < MM * WWD; i += 512)
        s_mem[(i >> 6) * 65 + (i & 63)] = g_mem[(long)b * MM * WWD + i];
    __syncthreads();

    if (tid < 4) {
        float a = s_xi[459 + tid * 3], bb2 = s_xi[460 + tid * 3], cc = s_xi[461 + tid * 3];
        float mx = fmaxf(a, fmaxf(bb2, cc));
        float ea = __expf(a - mx), eb = __expf(bb2 - mx), ec = __expf(cc - mx);
        float s = ea + eb + ec;
        s_rm[tid * 3] = __fdividef(ea, s);
        s_rm[tid * 3 + 1] = __fdividef(eb, s);
        s_rm[tid * 3 + 2] = __fdividef(ec, s);
    }

    // ---- usage update (old ww, old rw) ----
    float u = 0.f;
    if (tid < 256) {
        u = g_usage[b * 256 + m];
        u = u + (1.f - u) * s_wwo[m];
        float psi = 1.f;
        #pragma unroll
        for (int r = 0; r < 4; r++) psi *= 1.f - s_xi[453 + r] * s_rwo[r * 256 + m];
        u *= psi;
        g_usage[b * 256 + m] = u;
    }

    // ---- write content weights (OLD memory) ----
    float z = -1e30f;
    if (tid < 256) {
        float nk = 0.f, nm = 0.f, dot = 0.f;
        #pragma unroll 8
        for (int w = 0; w < 64; w++) {
            float kv = s_xi[260 + w];
            float mv = s_mem[m * 65 + w];
            nk += kv * kv; nm += mv * mv; dot += mv * kv;
        }
        nk = sqrtf(nk) + DELTA; nm = sqrtf(nm) + DELTA;
        z = __fdividef(dot, nm * nk) * s_xi[324];
    }
    float mx = red512_max(z, s_scr, tid);
    float e = (tid < 256) ? __expf(z - mx) : 0.f;
    float ssum = red512_sum(e, s_scr, tid);
    if (tid < 256) s_wcw[m] = __fdividef(e, ssum);

    // ---- allocation: stable ascending bitonic sort of u' ----
    if (tid < 256) { s_key[m] = DELTA + (1.f - DELTA) * u; s_idx[m] = m; }
    __syncthreads();
    for (int k = 2; k <= 256; k <<= 1) {
        for (int j = k >> 1; j > 0; j >>= 1) {
            if (tid < 256) {
                int l = tid ^ j;
                if (l > tid) {
                    bool up = ((tid & k) == 0);
                    float ki = s_key[tid], kl = s_key[l];
                    int ii = s_idx[tid], il = s_idx[l];
                    bool igt = (ki > kl) || (ki == kl && ii > il);
                    if (igt == up) { s_key[tid] = kl; s_key[l] = ki; s_idx[tid] = il; s_idx[l] = ii; }
                }
            }
            __syncthreads();
        }
    }
    if (tid < 256) s_red[tid] = s_key[tid];
    __syncthreads();
    for (int off = 1; off < 256; off <<= 1) {
        float prev = 1.f;
        if (tid < 256 && tid >= off) prev = s_red[tid - off];
        __syncthreads();
        if (tid < 256) s_red[tid] *= prev;
        __syncthreads();
    }
    if (tid < 256) {
        float excl = (tid == 0) ? 1.f : s_red[tid - 1];
        s_alloc[s_idx[tid]] = (1.f - s_key[tid]) * excl;
    }
    __syncthreads();

    // ---- new write weights ----
    float wwn = 0.f;
    if (tid < 256) {
        float ag = s_xi[457], wg = s_xi[458];
        wwn = wg * (ag * s_alloc[m] + (1.f - ag) * s_wcw[m]);
        s_ww[m] = wwn;
    }
    float sumww = red512_sum(wwn, s_scr, tid);   // contains syncs; s_ww visible after

    // ---- memory erase + write ----
    {
        int mm2 = tid >> 1, w0 = (tid & 1) * 32;
        float wv = s_ww[mm2];
        #pragma unroll 8
        for (int w = 0; w < 32; w++) {
            int idx = mm2 * 65 + w0 + w;
            s_mem[idx] = s_mem[idx] * (1.f - wv * s_xi[325 + w0 + w]) + wv * s_xi[389 + w0 + w];
        }
    }
    __syncthreads();
    for (int i = tid; i < MM * WWD; i += 512)
        g_mem[(long)b * MM * WWD + i] = s_mem[(i >> 6) * 65 + (i & 63)];

    // ---- link row pass: update + fwd (16 warps x 16 rows) ----
    float* lrow = g_link + (long)b * MM * MM;
    for (int ii = 0; ii < 16; ii++) {
        int i = warp * 16 + ii;
        float wwi = s_ww[i];
        float ps = 1.f - wwi;
        float f0 = 0.f, f1 = 0.f, f2 = 0.f, f3 = 0.f;
        #pragma unroll
        for (int it = 0; it < 2; it++) {
            int j0 = (it * 32 + lane) * 4;
            float4 lo = *(float4*)&lrow[i * 256 + j0];
            float4 wj = *(float4*)&s_ww[j0];
            float4 pj = *(float4*)&s_prec[j0];
            float4 ln;
            ln.x = (ps - wj.x) * lo.x + wwi * pj.x;
            ln.y = (ps - wj.y) * lo.y + wwi * pj.y;
            ln.z = (ps - wj.z) * lo.z + wwi * pj.z;
            ln.w = (ps - wj.w) * lo.w + wwi * pj.w;
            if (j0 + 0 == i) ln.x = 0.f;
            if (j0 + 1 == i) ln.y = 0.f;
            if (j0 + 2 == i) ln.z = 0.f;
            if (j0 + 3 == i) ln.w = 0.f;
            *(float4*)&lrow[i * 256 + j0] = ln;
            float4 r0v = *(float4*)&s_rwo[j0];
            float4 r1v = *(float4*)&s_rwo[256 + j0];
            float4 r2v = *(float4*)&s_rwo[512 + j0];
            float4 r3v = *(float4*)&s_rwo[768 + j0];
            f0 += ln.x * r0v.x + ln.y * r0v.y + ln.z * r0v.z + ln.w * r0v.w;
            f1 += ln.x * r1v.x + ln.y * r1v.y + ln.z * r1v.z + ln.w * r1v.w;
            f2 += ln.x * r2v.x + ln.y * r2v.y + ln.z * r2v.z + ln.w * r2v.w;
            f3 += ln.x * r3v.x + ln.y * r3v.y + ln.z * r3v.z + ln.w * r3v.w;
        }
        #pragma unroll
        for (int o = 16; o > 0; o >>= 1) {
            f0 += __shfl_xor_sync(0xffffffffu, f0, o);
            f1 += __shfl_xor_sync(0xffffffffu, f1, o);
            f2 += __shfl_xor_sync(0xffffffffu, f2, o);
            f3 += __shfl_xor_sync(0xffffffffu, f3, o);
        }
        if (lane == 0) {
            s_fwd[i] = f0; s_fwd[256 + i] = f1; s_fwd[512 + i] = f2; s_fwd[768 + i] = f3;
        }
    }
    __syncthreads();

    // ---- bwd column pass over NEW link (two-phase smem combine, no atomics) ----
    {
        int jb = (warp & 7) * 32 + lane;
        int ibase = (warp >> 3) * 128;
        float b0 = 0.f, b1 = 0.f, b2 = 0.f, b3 = 0.f;
        #pragma unroll 4
        for (int i = 0; i < 128; i++) {
            float lv = lrow[(ibase + i) * 256 + jb];
            b0 += s_rwo[ibase + i] * lv;
            b1 += s_rwo[256 + ibase + i] * lv;
            b2 += s_rwo[512 + ibase + i] * lv;
            b3 += s_rwo[768 + ibase + i] * lv;
        }
        if (warp < 8) {
            s_bwd[jb] = b0; s_bwd[256 + jb] = b1; s_bwd[512 + jb] = b2; s_bwd[768 + jb] = b3;
        }
        __syncthreads();
        if (warp >= 8) {
            s_bwd[jb] += b0; s_bwd[256 + jb] += b1; s_bwd[512 + jb] += b2; s_bwd[768 + jb] += b3;
        }
        __syncthreads();
    }

    // ---- precedence + ww stores ----
    if (tid < 256) {
        g_prec[b * 256 + m] = (1.f - sumww) * s_prec[m] + s_ww[m];
        g_ww[b * 256 + m] = s_ww[m];
    }

    // ---- read content weights (NEW memory), 4 heads in parallel ----
    const int r0 = tid >> 8;             // thread handles heads r0 and r0+2 at slot m
    float nk0 = 0.f, nk1 = 0.f;
    #pragma unroll 8
    for (int w = 0; w < 64; w++) {
        float k0v = s_xi[r0 * 64 + w], k1v = s_xi[(r0 + 2) * 64 + w];
        nk0 += k0v * k0v; nk1 += k1v * k1v;
    }
    nk0 = sqrtf(nk0) + DELTA; nk1 = sqrtf(nk1) + DELTA;
    float nm2 = 0.f, d0 = 0.f, d1 = 0.f;
    #pragma unroll 8
    for (int w = 0; w < 64; w++) {
        float mv = s_mem[m * 65 + w];
        nm2 += mv * mv;
        d0 += mv * s_xi[r0 * 64 + w];
        d1 += mv * s_xi[(r0 + 2) * 64 + w];
    }
    nm2 = sqrtf(nm2) + DELTA;
    float z0 = __fdividef(d0, nm2 * nk0) * s_xi[256 + r0];
    float z1 = __fdividef(d1, nm2 * nk1) * s_xi[256 + r0 + 2];

    {   // max over m per head (warps 0-7: heads 0&2, warps 8-15: heads 1&3)
        float w0 = z0, w1 = z1;
        #pragma unroll
        for (int o = 16; o > 0; o >>= 1) {
            w0 = fmaxf(w0, __shfl_xor_sync(0xffffffffu, w0, o));
            w1 = fmaxf(w1, __shfl_xor_sync(0xffffffffu, w1, o));
        }
        if (lane == 0) { s_scr[warp] = w0; s_scr[16 + warp] = w1; }
    }
    __syncthreads();
    if (tid < 32) {
        float v = s_scr[tid];
        v = fmaxf(v, __shfl_xor_sync(0xffffffffu, v, 4, 8));
        v = fmaxf(v, __shfl_xor_sync(0xffffffffu, v, 2, 8));
        v = fmaxf(v, __shfl_xor_sync(0xffffffffu, v, 1, 8));
        if ((tid & 7) == 0) s_scr[32 + (tid >> 3)] = v;   // heads 0,1,2,3
    }
    __syncthreads();
    float e0 = __expf(z0 - s_scr[32 + r0]);
    float e1 = __expf(z1 - s_scr[34 + r0]);
    {
        float w0 = e0, w1 = e1;
        #pragma unroll
        for (int o = 16; o > 0; o >>= 1) {
            w0 += __shfl_xor_sync(0xffffffffu, w0, o);
            w1 += __shfl_xor_sync(0xffffffffu, w1, o);
        }
        if (lane == 0) { s_scr[40 + warp] = w0; s_scr[56 + warp] = w1; }
    }
    __syncthreads();
    if (tid < 32) {
        float v = s_scr[40 + tid];
        v += __shfl_xor_sync(0xffffffffu, v, 4, 8);
        v += __shfl_xor_sync(0xffffffffu, v, 2, 8);
        v += __shfl_xor_sync(0xffffffffu, v, 1, 8);
        if ((tid & 7) == 0) s_scr[72 + (tid >> 3)] = v;   // heads 0,1,2,3
    }
    __syncthreads();
    float rc0 = __fdividef(e0, s_scr[72 + r0]);
    float rc1 = __fdividef(e1, s_scr[74 + r0]);

    // ---- new read weights ----
    {
        int rA = r0, rB = r0 + 2;
        float rnA = s_rm[rA * 3] * s_bwd[rA * 256 + m]
                  + s_rm[rA * 3 + 1] * s_fwd[rA * 256 + m]
                  + s_rm[rA * 3 + 2] * rc0;
        float rnB = s_rm[rB * 3] * s_bwd[rB * 256 + m]
                  + s_rm[rB * 3 + 1] * s_fwd[rB * 256 + m]
                  + s_rm[rB * 3 + 2] * rc1;
        s_rwn[rA * 256 + m] = rnA;
        s_rwn[rB * 256 + m] = rnB;
        g_rw[b * 1024 + rA * 256 + m] = rnA;
        g_rw[b * 1024 + rB * 256 + m] = rnB;
    }
    __syncthreads();

    // ---- read vectors (2 threads per output element) ----
    {
        int o = tid & 255, half = tid >> 8;
        int r = o >> 6, w = o & 63;
        float acc = 0.f;
        int mstart = half * 128;
        #pragma unroll 4
        for (int mm2 = mstart; mm2 < mstart + 128; mm2++)
            acc += s_rwn[r * 256 + mm2] * s_mem[mm2 * 65 + w];
        s_red[tid] = acc;
    }
    __syncthreads();
    if (tid < 256)
        g_ys[((long)(b * TT + t)) * NNOUT + 512 + tid] = s_red[tid] + s_red[tid + 256];
}

// ---------------- host orchestration ----------------
extern "C" void kernel_launch(void* const* d_in, const int* in_sizes, int n_in,
                              void* d_out, int out_size)
{
    const float* x    = (const float*)d_in[0];
    const float* h0   = (const float*)d_in[1];
    const float* Wih0 = (const float*)d_in[2];
    const float* Whh0 = (const float*)d_in[3];
    const float* bih0 = (const float*)d_in[4];
    const float* bhh0 = (const float*)d_in[5];
    const float* Wih1 = (const float*)d_in[6];
    const float* Whh1 = (const float*)d_in[7];
    const float* bih1 = (const float*)d_in[8];
    const float* bhh1 = (const float*)d_in[9];
    const float* Wif  = (const float*)d_in[10];
    const float* bif  = (const float*)d_in[11];
    const float* Wout = (const float*)d_in[12];
    const float* bout = (const float*)d_in[13];
    float* out = (float*)d_out;
    (void)in_sizes; (void)n_in; (void)out_size;

    (void)cudaFuncSetAttribute(mem_kernel, cudaFuncAttributeMaxDynamicSharedMemorySize,
                               MEM_SMEM_FLOATS * 4);

    float *p_px, *p_h0, *p_in1, *p_outb, *p_ys, *p_Wih0p, *p_bp0, *p_xprojp;
    cudaGetSymbolAddress((void**)&p_xprojp, g_xprojp);
    cudaGetSymbolAddress((void**)&p_px, g_px);
    cudaGetSymbolAddress((void**)&p_h0, g_h0buf);
    cudaGetSymbolAddress((void**)&p_in1, g_in1);
    cudaGetSymbolAddress((void**)&p_outb, g_outb);
    cudaGetSymbolAddress((void**)&p_ys, g_ys);
    cudaGetSymbolAddress((void**)&p_Wih0p, g_Wih0p);
    cudaGetSymbolAddress((void**)&p_bp0, g_bp0);

    init_kernel<<<16384, 256>>>(h0, Wih0, Whh0, bih0, bhh0, Wih1, Whh1, bih1, bhh1);

    // xprojp: (B*T,256) @ Wih0p^T + bp0 -> [b*T+t][4h+g]
    gemm_bt<<<dim3(G4H / 32, (BB * TT) / 64, 1), 256>>>(
        x, 256, p_Wih0p, 256, p_xprojp, G4H, 0L, G4H, 256, p_bp0, 0);

    const long ZX = (long)BB * 480;

    for (int t = 0; t < TT; t++) {
        int p = t & 1;
        lstm0_kernel<<<128, 512>>>(t, p_h0 + p * (BB * HH),
                                   p_h0 + (p ^ 1) * (BB * HH),
                                   p_in1 + p * (BB * 1024));
        lstm1_kernel<<<128, 512>>>(t, p_in1 + p * (BB * 1024),
                                   p_in1 + (p ^ 1) * (BB * 1024));
        gemm_bt<<<dim3(15, 1, 2), 256>>>(
            p_outb, 512, Wif, 512, p_px, 480, ZX, IFACE, 256, nullptr, 0);
        mem_kernel<<<BB, 512, MEM_SMEM_FLOATS * 4>>>(t, bif);
    }

    // final: out = tanh(ys) @ Wout^T + bout (tanh folded into A-load)
    gemm_bt<<<dim3(256 / 32, (BB * TT) / 64, 1), 256>>>(
        p_ys, NNOUT, Wout, NNOUT, out, 256, 0L, 256, NNOUT, bout, 1);
}

// round 13
// speedup vs baseline: 1.2297x; 1.2297x over previous
#include <cuda_runtime.h>
#include <math.h>

// ---------------- problem constants ----------------
#define BB 64
#define TT 32
#define HH 512
#define MM 256
#define WWD 64
#define RR 4
#define IFACE 471
#define G4H 2048
#define NNOUT 768
#define CLIPV 20.0f
#define DELTA 1e-6f
#define PXZ (BB*480)          // split-K partial stride inside one parity buffer
#define PXPAR (2*BB*480)      // parity stride

// ---------------- device state ----------------
__device__ float g_xprojp[BB*TT*G4H];   // permuted x-projection incl. biases, [b*T+t][4h+g]
__device__ float g_px[2*2*BB*480];      // [parity][splitK][b][480]
__device__ float g_h0buf[2*BB*HH];      // parity buffers for h0
__device__ float g_in1[2*BB*1024];      // parity buffers for [h0 | h1]
__device__ float g_c0[BB*HH];
__device__ float g_c1[BB*HH];
__device__ float g_outb[2*BB*HH];       // parity buffers (read by async px)
__device__ float g_mem[BB*MM*WWD];
__device__ float g_link[BB*MM*MM];
__device__ float g_prec[BB*MM];
__device__ float g_rw[BB*RR*MM];
__device__ float g_ww[BB*MM];
__device__ float g_usage[BB*MM];
__device__ float g_ys[BB*TT*NNOUT];
__device__ float g_W0p[G4H*512];        // permuted Whh0  (row n'=4h+g)
__device__ float g_Wih0p[G4H*256];      // permuted Wih0[:, :256]
__device__ float g_W1p[G4H*1024];       // permuted [Wih1 | Whh1]
__device__ float g_bp0[G4H];
__device__ float g_bp1[G4H];

// ---------------- fast-math helpers ----------------
__device__ __forceinline__ float sigf(float x) {
    return __fdividef(1.f, 1.f + __expf(-x));
}
__device__ __forceinline__ float tanhfast(float x) {
    float e = __expf(-2.f * fabsf(x));
    float r = __fdividef(1.f - e, 1.f + e);
    return copysignf(r, x);
}
__device__ __forceinline__ float splusf(float x) {
    return fmaxf(x, 0.f) + log1pf(__expf(-fabsf(x)));
}

// ---------------- generic C = A * B^T (B row-major [N][K]) ----------------
// Software-pipelined: next k-tile prefetched into registers before compute.
#define TKC 16
__global__ void __launch_bounds__(256) gemm_bt(
                        const float* __restrict__ A, int lda,
                        const float* __restrict__ Bw, int ldb,
                        float* __restrict__ C, int ldc, long zstride,
                        int N, int Klen,
                        const float* __restrict__ bias0,
                        int tanhA)
{
    __shared__ float As[TKC][68];
    __shared__ __align__(16) float Bs[TKC][34];

    const int tid = threadIdx.x;
    const int tx = tid & 15;
    const int ty = tid >> 4;
    const int row0 = blockIdx.y * 64;
    const int n0 = blockIdx.x * 32;
    const int kstart = blockIdx.z * Klen;
    C += (long)blockIdx.z * zstride;

    float acc[4][2] = {};

    const int la_m = tid >> 2;
    const int la_k = (tid & 3) * 4;
    const int lb_n = tid >> 3;
    const int lb_k = (tid & 7) * 2;

    const float* Ab = A + (long)(row0 + la_m) * lda + kstart + la_k;
    const bool bvalid = (n0 + lb_n) < N;
    const float* Bb = Bw + (long)(n0 + lb_n) * ldb + kstart + lb_k;

    float a0 = Ab[0], a1 = Ab[1], a2 = Ab[2], a3 = Ab[3];
    float b0 = 0.f, b1 = 0.f;
    if (bvalid) { b0 = Bb[0]; b1 = Bb[1]; }

    for (int k0 = 0; k0 < Klen; k0 += TKC) {
        float sa0 = a0, sa1 = a1, sa2 = a2, sa3 = a3;
        if (tanhA) { sa0 = tanhfast(sa0); sa1 = tanhfast(sa1);
                     sa2 = tanhfast(sa2); sa3 = tanhfast(sa3); }
        __syncthreads();
        As[la_k + 0][la_m] = sa0; As[la_k + 1][la_m] = sa1;
        As[la_k + 2][la_m] = sa2; As[la_k + 3][la_m] = sa3;
        Bs[lb_k][lb_n] = b0; Bs[lb_k + 1][lb_n] = b1;
        __syncthreads();
        if (k0 + TKC < Klen) {
            a0 = Ab[k0 + TKC + 0]; a1 = Ab[k0 + TKC + 1];
            a2 = Ab[k0 + TKC + 2]; a3 = Ab[k0 + TKC + 3];
            if (bvalid) { b0 = Bb[k0 + TKC]; b1 = Bb[k0 + TKC + 1]; }
        }
        #pragma unroll
        for (int kk = 0; kk < TKC; kk++) {
            float4 av = *(const float4*)&As[kk][ty * 4];
            float2 bv = *(const float2*)&Bs[kk][tx * 2];
            acc[0][0] += av.x * bv.x; acc[0][1] += av.x * bv.y;
            acc[1][0] += av.y * bv.x; acc[1][1] += av.y * bv.y;
            acc[2][0] += av.z * bv.x; acc[2][1] += av.z * bv.y;
            acc[3][0] += av.w * bv.x; acc[3][1] += av.w * bv.y;
        }
    }
    #pragma unroll
    for (int i = 0; i < 4; i++) {
        int m = row0 + ty * 4 + i;
        #pragma unroll
        for (int j = 0; j < 2; j++) {
            int n = n0 + tx * 2 + j;
            if (n < N) {
                float v = acc[i][j];
                if (bias0) v += bias0[n];
                C[(long)m * ldc + n] = v;
            }
        }
    }
}

// ---------------- init: permute weights + init state ----------------
__global__ void __launch_bounds__(256) init_kernel(
                            const float* __restrict__ h0in,
                            const float* __restrict__ Wih0,
                            const float* __restrict__ Whh0,
                            const float* __restrict__ bih0,
                            const float* __restrict__ bhh0,
                            const float* __restrict__ Wih1,
                            const float* __restrict__ Whh1,
                            const float* __restrict__ bih1,
                            const float* __restrict__ bhh1)
{
    int i = blockIdx.x * 256 + threadIdx.x;
    if (i < BB * MM * MM) g_link[i] = 0.f;
    if (i < BB * MM * WWD) g_mem[i] = DELTA;
    if (i < G4H * 1024) {
        int n = i >> 10, k = i & 1023;
        int h = n >> 2, g = n & 3;
        g_W1p[i] = (k < 512) ? Wih1[(g * 512 + h) * 512 + k]
                             : Whh1[(g * 512 + h) * 512 + (k - 512)];
    }
    if (i < G4H * 512) {
        int n = i >> 9, k = i & 511;
        int h = n >> 2, g = n & 3;
        g_W0p[i] = Whh0[(g * 512 + h) * 512 + k];
    }
    if (i < G4H * 256) {
        int n = i >> 8, k = i & 255;
        int h = n >> 2, g = n & 3;
        g_Wih0p[i] = Wih0[(g * 512 + h) * 512 + k];
    }
    if (i < G4H) {
        int h = i >> 2, g = i & 3;
        g_bp0[i] = bih0[g * 512 + h] + bhh0[g * 512 + h];
        g_bp1[i] = bih1[g * 512 + h] + bhh1[g * 512 + h];
    }
    if (i < BB * HH) {
        g_h0buf[i] = h0in[i];
        g_c0[i] = h0in[i];
        g_c1[i] = h0in[32768 + i];
    }
    if (i < BB * 1024) {
        int b = i >> 10, c = i & 1023;
        if (c >= 512) g_in1[i] = h0in[32768 + b * 512 + (c - 512)];
    }
    if (i < BB * RR * MM) g_rw[i] = DELTA;
    if (i < BB * MM) { g_ww[i] = DELTA; g_usage[i] = 0.f; g_prec[i] = 0.f; }
}

// ---------------- fused GEMM + LSTM cell kernels (Round-10 proven) ----------
// Tile: 64 batch rows x 16 gate-cols (= 4 h), K-tile 32, 256 threads.
// Thread (r=tid&63, q=tid>>6) owns all 4 gates of (b=r, h=blk*4+q); cell in epilogue.
__global__ void __launch_bounds__(256) lstm0_kernel(
                             int t, const float* __restrict__ A,
                             float* __restrict__ h0next, float* __restrict__ in1cur)
{
    __shared__ float As[32][65];
    __shared__ __align__(16) float Bs[32][20];
    const int tid = threadIdx.x;
    const int r = tid & 63, q = tid >> 6;
    const int n0 = blockIdx.x * 16;
    const int a_row = tid >> 2, a_kb = (tid & 3) * 8;
    const int b_n = tid >> 4, b_k2 = (tid & 15) * 2;
    const float* Ap = A + a_row * 512 + a_kb;
    const float* Bp = g_W0p + (n0 + b_n) * 512 + b_k2;
    float acc0 = 0.f, acc1 = 0.f, acc2 = 0.f, acc3 = 0.f;

    float4 ra0 = *(const float4*)(Ap);
    float4 ra1 = *(const float4*)(Ap + 4);
    float rb0 = Bp[0], rb1 = Bp[1];

    #pragma unroll 1
    for (int k0 = 0; k0 < 512; k0 += 32) {
        __syncthreads();
        As[a_kb + 0][a_row] = ra0.x; As[a_kb + 1][a_row] = ra0.y;
        As[a_kb + 2][a_row] = ra0.z; As[a_kb + 3][a_row] = ra0.w;
        As[a_kb + 4][a_row] = ra1.x; As[a_kb + 5][a_row] = ra1.y;
        As[a_kb + 6][a_row] = ra1.z; As[a_kb + 7][a_row] = ra1.w;
        Bs[b_k2][b_n] = rb0; Bs[b_k2 + 1][b_n] = rb1;
        __syncthreads();
        if (k0 + 32 < 512) {
            ra0 = *(const float4*)(Ap + k0 + 32);
            ra1 = *(const float4*)(Ap + k0 + 36);
            rb0 = Bp[k0 + 32]; rb1 = Bp[k0 + 33];
        }
        #pragma unroll
        for (int kk = 0; kk < 32; kk++) {
            float a = As[kk][r];
            float4 b4 = *(const float4*)&Bs[kk][q * 4];
            acc0 += a * b4.x; acc1 += a * b4.y; acc2 += a * b4.z; acc3 += a * b4.w;
        }
    }
    int h = blockIdx.x * 4 + q;
    float4 xp = *(const float4*)&g_xprojp[((long)(r * TT + t)) * G4H + h * 4];
    float gi = acc0 + xp.x, gf = acc1 + xp.y, gg = acc2 + xp.z, go = acc3 + xp.w;
    float c = sigf(gf) * g_c0[r * 512 + h] + sigf(gi) * tanhfast(gg);
    g_c0[r * 512 + h] = c;
    float hh = sigf(go) * tanhfast(c);
    h0next[r * 512 + h] = hh;
    in1cur[r * 1024 + h] = hh;
}

__global__ void __launch_bounds__(256) lstm1_kernel(
                             int t, const float* __restrict__ A,
                             float* __restrict__ in1next,
                             float* __restrict__ outb)
{
    __shared__ float As[32][65];
    __shared__ __align__(16) float Bs[32][20];
    const int tid = threadIdx.x;
    const int r = tid & 63, q = tid >> 6;
    const int n0 = blockIdx.x * 16;
    const int a_row = tid >> 2, a_kb = (tid & 3) * 8;
    const int b_n = tid >> 4, b_k2 = (tid & 15) * 2;
    const float* Ap = A + a_row * 1024 + a_kb;
    const float* Bp = g_W1p + (n0 + b_n) * 1024 + b_k2;
    float acc0 = 0.f, acc1 = 0.f, acc2 = 0.f, acc3 = 0.f;

    float4 ra0 = *(const float4*)(Ap);
    float4 ra1 = *(const float4*)(Ap + 4);
    float rb0 = Bp[0], rb1 = Bp[1];

    #pragma unroll 1
    for (int k0 = 0; k0 < 1024; k0 += 32) {
        __syncthreads();
        As[a_kb + 0][a_row] = ra0.x; As[a_kb + 1][a_row] = ra0.y;
        As[a_kb + 2][a_row] = ra0.z; As[a_kb + 3][a_row] = ra0.w;
        As[a_kb + 4][a_row] = ra1.x; As[a_kb + 5][a_row] = ra1.y;
        As[a_kb + 6][a_row] = ra1.z; As[a_kb + 7][a_row] = ra1.w;
        Bs[b_k2][b_n] = rb0; Bs[b_k2 + 1][b_n] = rb1;
        __syncthreads();
        if (k0 + 32 < 1024) {
            ra0 = *(const float4*)(Ap + k0 + 32);
            ra1 = *(const float4*)(Ap + k0 + 36);
            rb0 = Bp[k0 + 32]; rb1 = Bp[k0 + 33];
        }
        #pragma unroll
        for (int kk = 0; kk < 32; kk++) {
            float a = As[kk][r];
            float4 b4 = *(const float4*)&Bs[kk][q * 4];
            acc0 += a * b4.x; acc1 += a * b4.y; acc2 += a * b4.z; acc3 += a * b4.w;
        }
    }
    int h = blockIdx.x * 4 + q;
    float4 bi = *(const float4*)&g_bp1[h * 4];
    float gi = acc0 + bi.x, gf = acc1 + bi.y, gg = acc2 + bi.z, go = acc3 + bi.w;
    float c = sigf(gf) * g_c1[r * 512 + h] + sigf(gi) * tanhfast(gg);
    g_c1[r * 512 + h] = c;
    float h1 = sigf(go) * tanhfast(c);
    in1next[r * 1024 + 512 + h] = h1;
    float o = fminf(fmaxf(h1, -CLIPV), CLIPV);
    outb[r * 512 + h] = o;
    g_ys[((long)(r * TT + t)) * NNOUT + h] = o;
}

// ---------------- memory step: one block (512 thr) per batch ----------------
#define MEM_SMEM_FLOATS (256*65 + 4*1024 + 6*256 + 256 + 480 + 512 + 16 + 96)

__device__ __forceinline__ float red512_max(float v, float* s_scr, int tid) {
    #pragma unroll
    for (int o = 16; o > 0; o >>= 1) v = fmaxf(v, __shfl_xor_sync(0xffffffffu, v, o));
    if ((tid & 31) == 0) s_scr[tid >> 5] = v;
    __syncthreads();
    if (tid < 32) {
        float x = (tid < 16) ? s_scr[tid] : -1e30f;
        #pragma unroll
        for (int o = 8; o > 0; o >>= 1) x = fmaxf(x, __shfl_xor_sync(0xffffffffu, x, o));
        if (tid == 0) s_scr[0] = x;
    }
    __syncthreads();
    float rr = s_scr[0];
    __syncthreads();
    return rr;
}
__device__ __forceinline__ float red512_sum(float v, float* s_scr, int tid) {
    #pragma unroll
    for (int o = 16; o > 0; o >>= 1) v += __shfl_xor_sync(0xffffffffu, v, o);
    if ((tid & 31) == 0) s_scr[tid >> 5] = v;
    __syncthreads();
    if (tid < 32) {
        float x = (tid < 16) ? s_scr[tid] : 0.f;
        #pragma unroll
        for (int o = 8; o > 0; o >>= 1) x += __shfl_xor_sync(0xffffffffu, x, o);
        if (tid == 0) s_scr[0] = x;
    }
    __syncthreads();
    float rr = s_scr[0];
    __syncthreads();
    return rr;
}

__global__ void __launch_bounds__(512) mem_kernel(int t, const float* __restrict__ bif,
                                                  const float* __restrict__ pxb)
{
    extern __shared__ float sm[];
    float* s_mem  = sm;                     // 256*65
    float* s_rwo  = s_mem + 256 * 65;       // 1024
    float* s_rwn  = s_rwo + 1024;           // 1024
    float* s_fwd  = s_rwn + 1024;           // 1024
    float* s_bwd  = s_fwd + 1024;           // 1024
    float* s_ww   = s_bwd + 1024;           // 256
    float* s_wwo  = s_ww + 256;
    float* s_prec = s_wwo + 256;
    float* s_alloc= s_prec + 256;
    float* s_wcw  = s_alloc + 256;
    float* s_key  = s_wcw + 256;
    int*   s_idx  = (int*)(s_key + 256);    // 256
    float* s_xi   = (float*)(s_idx + 256);  // 480
    float* s_red  = s_xi + 480;             // 512
    float* s_rm   = s_red + 512;            // 16
    float* s_scr  = s_rm + 16;              // 96

    const int tid = threadIdx.x;
    const int b = blockIdx.x;
    const int m = tid & 255;
    const int warp = tid >> 5, lane = tid & 31;

    // ---- loads + xi activations ----
    for (int i = tid; i < IFACE; i += 512) {
        float v = bif[i] + pxb[b * 480 + i] + pxb[PXZ + b * 480 + i];
        if      (i < 256) v = tanhfast(v);
        else if (i < 260) v = splusf(v);
        else if (i < 324) v = tanhfast(v);
        else if (i == 324) v = splusf(v);
        else if (i < 389) v = sigf(v);
        else if (i < 453) v = tanhfast(v);
        else if (i < 459) v = sigf(v);
        s_xi[i] = v;
    }
    for (int i = tid; i < 1024; i += 512) s_rwo[i] = g_rw[b * 1024 + i];
    if (tid < 256) {
        s_wwo[tid]  = g_ww[b * 256 + tid];
        s_prec[tid] = g_prec[b * 256 + tid];
    }
    for (int i = tid; i < MM * WWD; i += 512)
        s_mem[(i >> 6) * 65 + (i & 63)] = g_mem[(long)b * MM * WWD + i];
    __syncthreads();

    if (tid < 4) {
        float a = s_xi[459 + tid * 3], bb2 = s_xi[460 + tid * 3], cc = s_xi[461 + tid * 3];
        float mx = fmaxf(a, fmaxf(bb2, cc));
        float ea = __expf(a - mx), eb = __expf(bb2 - mx), ec = __expf(cc - mx);
        float s = ea + eb + ec;
        s_rm[tid * 3] = __fdividef(ea, s);
        s_rm[tid * 3 + 1] = __fdividef(eb, s);
        s_rm[tid * 3 + 2] = __fdividef(ec, s);
    }

    // ---- usage update (old ww, old rw) ----
    float u = 0.f;
    if (tid < 256) {
        u = g_usage[b * 256 + m];
        u = u + (1.f - u) * s_wwo[m];
        float psi = 1.f;
        #pragma unroll
        for (int r = 0; r < 4; r++) psi *= 1.f - s_xi[453 + r] * s_rwo[r * 256 + m];
        u *= psi;
        g_usage[b * 256 + m] = u;
    }

    // ---- write content weights (OLD memory) ----
    float z = -1e30f;
    if (tid < 256) {
        float nk = 0.f, nm = 0.f, dot = 0.f;
        #pragma unroll 8
        for (int w = 0; w < 64; w++) {
            float kv = s_xi[260 + w];
            float mv = s_mem[m * 65 + w];
            nk += kv * kv; nm += mv * mv; dot += mv * kv;
        }
        nk = sqrtf(nk) + DELTA; nm = sqrtf(nm) + DELTA;
        z = __fdividef(dot, nm * nk) * s_xi[324];
    }
    float mx = red512_max(z, s_scr, tid);
    float e = (tid < 256) ? __expf(z - mx) : 0.f;
    float ssum = red512_sum(e, s_scr, tid);
    if (tid < 256) s_wcw[m] = __fdividef(e, ssum);

    // ---- allocation: stable ascending bitonic sort of u' ----
    if (tid < 256) { s_key[m] = DELTA + (1.f - DELTA) * u; s_idx[m] = m; }
    __syncthreads();
    for (int k = 2; k <= 256; k <<= 1) {
        for (int j = k >> 1; j > 0; j >>= 1) {
            if (tid < 256) {
                int l = tid ^ j;
                if (l > tid) {
                    bool up = ((tid & k) == 0);
                    float ki = s_key[tid], kl = s_key[l];
                    int ii = s_idx[tid], il = s_idx[l];
                    bool igt = (ki > kl) || (ki == kl && ii > il);
                    if (igt == up) { s_key[tid] = kl; s_key[l] = ki; s_idx[tid] = il; s_idx[l] = ii; }
                }
            }
            __syncthreads();
        }
    }
    if (tid < 256) s_red[tid] = s_key[tid];
    __syncthreads();
    for (int off = 1; off < 256; off <<= 1) {
        float prev = 1.f;
        if (tid < 256 && tid >= off) prev = s_red[tid - off];
        __syncthreads();
        if (tid < 256) s_red[tid] *= prev;
        __syncthreads();
    }
    if (tid < 256) {
        float excl = (tid == 0) ? 1.f : s_red[tid - 1];
        s_alloc[s_idx[tid]] = (1.f - s_key[tid]) * excl;
    }
    __syncthreads();

    // ---- new write weights ----
    float wwn = 0.f;
    if (tid < 256) {
        float ag = s_xi[457], wg = s_xi[458];
        wwn = wg * (ag * s_alloc[m] + (1.f - ag) * s_wcw[m]);
        s_ww[m] = wwn;
    }
    float sumww = red512_sum(wwn, s_scr, tid);   // contains syncs; s_ww visible after

    // ---- memory erase + write ----
    {
        int mm2 = tid >> 1, w0 = (tid & 1) * 32;
        float wv = s_ww[mm2];
        #pragma unroll 8
        for (int w = 0; w < 32; w++) {
            int idx = mm2 * 65 + w0 + w;
            s_mem[idx] = s_mem[idx] * (1.f - wv * s_xi[325 + w0 + w]) + wv * s_xi[389 + w0 + w];
        }
    }
    __syncthreads();
    for (int i = tid; i < MM * WWD; i += 512)
        g_mem[(long)b * MM * WWD + i] = s_mem[(i >> 6) * 65 + (i & 63)];

    // ---- link row pass: update + fwd (16 warps x 16 rows) ----
    float* lrow = g_link + (long)b * MM * MM;
    for (int ii = 0; ii < 16; ii++) {
        int i = warp * 16 + ii;
        float wwi = s_ww[i];
        float ps = 1.f - wwi;
        float f0 = 0.f, f1 = 0.f, f2 = 0.f, f3 = 0.f;
        #pragma unroll
        for (int it = 0; it < 2; it++) {
            int j0 = (it * 32 + lane) * 4;
            float4 lo = *(float4*)&lrow[i * 256 + j0];
            float4 wj = *(float4*)&s_ww[j0];
            float4 pj = *(float4*)&s_prec[j0];
            float4 ln;
            ln.x = (ps - wj.x) * lo.x + wwi * pj.x;
            ln.y = (ps - wj.y) * lo.y + wwi * pj.y;
            ln.z = (ps - wj.z) * lo.z + wwi * pj.z;
            ln.w = (ps - wj.w) * lo.w + wwi * pj.w;
            if (j0 + 0 == i) ln.x = 0.f;
            if (j0 + 1 == i) ln.y = 0.f;
            if (j0 + 2 == i) ln.z = 0.f;
            if (j0 + 3 == i) ln.w = 0.f;
            *(float4*)&lrow[i * 256 + j0] = ln;
            float4 r0v = *(float4*)&s_rwo[j0];
            float4 r1v = *(float4*)&s_rwo[256 + j0];
            float4 r2v = *(float4*)&s_rwo[512 + j0];
            float4 r3v = *(float4*)&s_rwo[768 + j0];
            f0 += ln.x * r0v.x + ln.y * r0v.y + ln.z * r0v.z + ln.w * r0v.w;
            f1 += ln.x * r1v.x + ln.y * r1v.y + ln.z * r1v.z + ln.w * r1v.w;
            f2 += ln.x * r2v.x + ln.y * r2v.y + ln.z * r2v.z + ln.w * r2v.w;
            f3 += ln.x * r3v.x + ln.y * r3v.y + ln.z * r3v.z + ln.w * r3v.w;
        }
        #pragma unroll
        for (int o = 16; o > 0; o >>= 1) {
            f0 += __shfl_xor_sync(0xffffffffu, f0, o);
            f1 += __shfl_xor_sync(0xffffffffu, f1, o);
            f2 += __shfl_xor_sync(0xffffffffu, f2, o);
            f3 += __shfl_xor_sync(0xffffffffu, f3, o);
        }
        if (lane == 0) {
            s_fwd[i] = f0; s_fwd[256 + i] = f1; s_fwd[512 + i] = f2; s_fwd[768 + i] = f3;
        }
    }
    __syncthreads();

    // ---- bwd column pass over NEW link (two-phase smem combine, no atomics) ----
    {
        int jb = (warp & 7) * 32 + lane;
        int ibase = (warp >> 3) * 128;
        float b0 = 0.f, b1 = 0.f, b2 = 0.f, b3 = 0.f;
        #pragma unroll 4
        for (int i = 0; i < 128; i++) {
            float lv = lrow[(ibase + i) * 256 + jb];
            b0 += s_rwo[ibase + i] * lv;
            b1 += s_rwo[256 + ibase + i] * lv;
            b2 += s_rwo[512 + ibase + i] * lv;
            b3 += s_rwo[768 + ibase + i] * lv;
        }
        if (warp < 8) {
            s_bwd[jb] = b0; s_bwd[256 + jb] = b1; s_bwd[512 + jb] = b2; s_bwd[768 + jb] = b3;
        }
        __syncthreads();
        if (warp >= 8) {
            s_bwd[jb] += b0; s_bwd[256 + jb] += b1; s_bwd[512 + jb] += b2; s_bwd[768 + jb] += b3;
        }
        __syncthreads();
    }

    // ---- precedence + ww stores ----
    if (tid < 256) {
        g_prec[b * 256 + m] = (1.f - sumww) * s_prec[m] + s_ww[m];
        g_ww[b * 256 + m] = s_ww[m];
    }

    // ---- read content weights (NEW memory), 4 heads in parallel ----
    const int r0 = tid >> 8;             // thread handles heads r0 and r0+2 at slot m
    float nk0 = 0.f, nk1 = 0.f;
    #pragma unroll 8
    for (int w = 0; w < 64; w++) {
        float k0v = s_xi[r0 * 64 + w], k1v = s_xi[(r0 + 2) * 64 + w];
        nk0 += k0v * k0v; nk1 += k1v * k1v;
    }
    nk0 = sqrtf(nk0) + DELTA; nk1 = sqrtf(nk1) + DELTA;
    float nm2 = 0.f, d0 = 0.f, d1 = 0.f;
    #pragma unroll 8
    for (int w = 0; w < 64; w++) {
        float mv = s_mem[m * 65 + w];
        nm2 += mv * mv;
        d0 += mv * s_xi[r0 * 64 + w];
        d1 += mv * s_xi[(r0 + 2) * 64 + w];
    }
    nm2 = sqrtf(nm2) + DELTA;
    float z0 = __fdividef(d0, nm2 * nk0) * s_xi[256 + r0];
    float z1 = __fdividef(d1, nm2 * nk1) * s_xi[256 + r0 + 2];

    {   // max over m per head (warps 0-7: heads 0&2, warps 8-15: heads 1&3)
        float w0 = z0, w1 = z1;
        #pragma unroll
        for (int o = 16; o > 0; o >>= 1) {
            w0 = fmaxf(w0, __shfl_xor_sync(0xffffffffu, w0, o));
            w1 = fmaxf(w1, __shfl_xor_sync(0xffffffffu, w1, o));
        }
        if (lane == 0) { s_scr[warp] = w0; s_scr[16 + warp] = w1; }
    }
    __syncthreads();
    if (tid < 32) {
        float v = s_scr[tid];
        v = fmaxf(v, __shfl_xor_sync(0xffffffffu, v, 4, 8));
        v = fmaxf(v, __shfl_xor_sync(0xffffffffu, v, 2, 8));
        v = fmaxf(v, __shfl_xor_sync(0xffffffffu, v, 1, 8));
        if ((tid & 7) == 0) s_scr[32 + (tid >> 3)] = v;   // heads 0,1,2,3
    }
    __syncthreads();
    float e0 = __expf(z0 - s_scr[32 + r0]);
    float e1 = __expf(z1 - s_scr[34 + r0]);
    {
        float w0 = e0, w1 = e1;
        #pragma unroll
        for (int o = 16; o > 0; o >>= 1) {
            w0 += __shfl_xor_sync(0xffffffffu, w0, o);
            w1 += __shfl_xor_sync(0xffffffffu, w1, o);
        }
        if (lane == 0) { s_scr[40 + warp] = w0; s_scr[56 + warp] = w1; }
    }
    __syncthreads();
    if (tid < 32) {
        float v = s_scr[40 + tid];
        v += __shfl_xor_sync(0xffffffffu, v, 4, 8);
        v += __shfl_xor_sync(0xffffffffu, v, 2, 8);
        v += __shfl_xor_sync(0xffffffffu, v, 1, 8);
        if ((tid & 7) == 0) s_scr[72 + (tid >> 3)] = v;   // heads 0,1,2,3
    }
    __syncthreads();
    float rc0 = __fdividef(e0, s_scr[72 + r0]);
    float rc1 = __fdividef(e1, s_scr[74 + r0]);

    // ---- new read weights ----
    {
        int rA = r0, rB = r0 + 2;
        float rnA = s_rm[rA * 3] * s_bwd[rA * 256 + m]
                  + s_rm[rA * 3 + 1] * s_fwd[rA * 256 + m]
                  + s_rm[rA * 3 + 2] * rc0;
        float rnB = s_rm[rB * 3] * s_bwd[rB * 256 + m]
                  + s_rm[rB * 3 + 1] * s_fwd[rB * 256 + m]
                  + s_rm[rB * 3 + 2] * rc1;
        s_rwn[rA * 256 + m] = rnA;
        s_rwn[rB * 256 + m] = rnB;
        g_rw[b * 1024 + rA * 256 + m] = rnA;
        g_rw[b * 1024 + rB * 256 + m] = rnB;
    }
    __syncthreads();

    // ---- read vectors (2 threads per output element) ----
    {
        int o = tid & 255, half = tid >> 8;
        int r = o >> 6, w = o & 63;
        float acc = 0.f;
        int mstart = half * 128;
        #pragma unroll 4
        for (int mm2 = mstart; mm2 < mstart + 128; mm2++)
            acc += s_rwn[r * 256 + mm2] * s_mem[mm2 * 65 + w];
        s_red[tid] = acc;
    }
    __syncthreads();
    if (tid < 256)
        g_ys[((long)(b * TT + t)) * NNOUT + 512 + tid] = s_red[tid] + s_red[tid + 256];
}

// ---------------- host orchestration ----------------
extern "C" void kernel_launch(void* const* d_in, const int* in_sizes, int n_in,
                              void* d_out, int out_size)
{
    const float* x    = (const float*)d_in[0];
    const float* h0   = (const float*)d_in[1];
    const float* Wih0 = (const float*)d_in[2];
    const float* Whh0 = (const float*)d_in[3];
    const float* bih0 = (const float*)d_in[4];
    const float* bhh0 = (const float*)d_in[5];
    const float* Wih1 = (const float*)d_in[6];
    const float* Whh1 = (const float*)d_in[7];
    const float* bih1 = (const float*)d_in[8];
    const float* bhh1 = (const float*)d_in[9];
    const float* Wif  = (const float*)d_in[10];
    const float* bif  = (const float*)d_in[11];
    const float* Wout = (const float*)d_in[12];
    const float* bout = (const float*)d_in[13];
    float* out = (float*)d_out;
    (void)in_sizes; (void)n_in; (void)out_size;

    // One-time resources (created on the eager correctness call, before capture).
    static cudaStream_t s2 = 0;
    static cudaEvent_t evFork = 0, evJoin0 = 0, evJoin1 = 0;
    if (!s2) {
        cudaStreamCreateWithFlags(&s2, cudaStreamNonBlocking);
        cudaEventCreateWithFlags(&evFork, cudaEventDisableTiming);
        cudaEventCreateWithFlags(&evJoin0, cudaEventDisableTiming);
        cudaEventCreateWithFlags(&evJoin1, cudaEventDisableTiming);
    }
    cudaEvent_t evJoin[2] = { evJoin0, evJoin1 };

    (void)cudaFuncSetAttribute(mem_kernel, cudaFuncAttributeMaxDynamicSharedMemorySize,
                               MEM_SMEM_FLOATS * 4);

    float *p_px, *p_h0, *p_in1, *p_outb, *p_ys, *p_Wih0p, *p_bp0, *p_xprojp;
    cudaGetSymbolAddress((void**)&p_xprojp, g_xprojp);
    cudaGetSymbolAddress((void**)&p_px, g_px);
    cudaGetSymbolAddress((void**)&p_h0, g_h0buf);
    cudaGetSymbolAddress((void**)&p_in1, g_in1);
    cudaGetSymbolAddress((void**)&p_outb, g_outb);
    cudaGetSymbolAddress((void**)&p_ys, g_ys);
    cudaGetSymbolAddress((void**)&p_Wih0p, g_Wih0p);
    cudaGetSymbolAddress((void**)&p_bp0, g_bp0);

    init_kernel<<<16384, 256>>>(h0, Wih0, Whh0, bih0, bhh0, Wih1, Whh1, bih1, bhh1);

    // xprojp: (B*T,256) @ Wih0p^T + bp0 -> [b*T+t][4h+g]
    gemm_bt<<<dim3(G4H / 32, (BB * TT) / 64, 1), 256>>>(
        x, 256, p_Wih0p, 256, p_xprojp, G4H, 0L, G4H, 256, p_bp0, 0);

    for (int t = 0; t < TT; t++) {
        int p = t & 1;
        // Reuse-guard: parity-p buffers (outb, px) were last consumed by the
        // s2 branch of step t-2; wait for its join before overwriting.
        if (t >= 2) cudaStreamWaitEvent(0, evJoin[p], 0);

        lstm0_kernel<<<128, 256>>>(t, p_h0 + p * (BB * HH),
                                   p_h0 + (p ^ 1) * (BB * HH),
                                   p_in1 + p * (BB * 1024));
        lstm1_kernel<<<128, 256>>>(t, p_in1 + p * (BB * 1024),
                                   p_in1 + (p ^ 1) * (BB * 1024),
                                   p_outb + p * (BB * HH));

        // Fork: px + mem run on s2, overlapped with the next step's LSTMs.
        cudaEventRecord(evFork, 0);
        cudaStreamWaitEvent(s2, evFork, 0);
        gemm_bt<<<dim3(15, 1, 2), 256, 0, s2>>>(
            p_outb + p * (BB * HH), 512, Wif, 512,
            p_px + p * PXPAR, 480, (long)PXZ, IFACE, 256, nullptr, 0);
        mem_kernel<<<BB, 512, MEM_SMEM_FLOATS * 4, s2>>>(t, bif, p_px + p * PXPAR);
        cudaEventRecord(evJoin[p], s2);
    }

    // Join the s2 branch (its stream order covers all earlier mem steps).
    cudaStreamWaitEvent(0, evJoin[(TT - 1) & 1], 0);

    // final: out = tanh(ys) @ Wout^T + bout (tanh folded into A-load)
    gemm_bt<<<dim3(256 / 32, (BB * TT) / 64, 1), 256>>>(
        p_ys, NNOUT, Wout, NNOUT, out, 256, 0L, 256, NNOUT, bout, 1);
}

// round 14
// speedup vs baseline: 1.4305x; 1.1633x over previous
#include <cuda_runtime.h>
#include <math.h>

// ---------------- problem constants ----------------
#define BB 64
#define TT 32
#define HH 512
#define MM 256
#define WWD 64
#define RR 4
#define IFACE 471
#define G4H 2048
#define NNOUT 768
#define CLIPV 20.0f
#define DELTA 1e-6f

// ---------------- device state ----------------
__device__ float g_xprojp[BB*TT*G4H];   // permuted x-projection incl. biases, [b*T+t][4h+g]
__device__ float g_p1h[BB*G4H];         // lstm1 partial: W1p[:,512:] @ h1_old
__device__ float g_h0buf[2*BB*HH];      // parity buffers for h0
__device__ float g_in1[2*BB*1024];      // parity buffers for [h0 | h1]
__device__ float g_c0[BB*HH];
__device__ float g_c1[BB*HH];
__device__ float g_outb[BB*HH];
__device__ float g_mem[BB*MM*WWD];
__device__ float g_link[BB*MM*MM];
__device__ float g_prec[BB*MM];
__device__ float g_rw[BB*RR*MM];
__device__ float g_ww[BB*MM];
__device__ float g_usage[BB*MM];
__device__ float g_ys[BB*TT*NNOUT];
__device__ float g_W0p[G4H*512];        // permuted Whh0  (row n'=4h+g)
__device__ float g_Wih0p[G4H*256];      // permuted Wih0[:, :256]
__device__ float g_W1p[G4H*1024];       // permuted [Wih1 | Whh1]
__device__ float g_WifT[512*480];       // transposed Wif: [k][i], i padded to 480
__device__ float g_bp0[G4H];
__device__ float g_bp1[G4H];

// ---------------- fast-math helpers ----------------
__device__ __forceinline__ float sigf(float x) {
    return __fdividef(1.f, 1.f + __expf(-x));
}
__device__ __forceinline__ float tanhfast(float x) {
    float e = __expf(-2.f * fabsf(x));
    float r = __fdividef(1.f - e, 1.f + e);
    return copysignf(r, x);
}
__device__ __forceinline__ float splusf(float x) {
    return fmaxf(x, 0.f) + log1pf(__expf(-fabsf(x)));
}

// ---------------- generic C = A * B^T (B row-major [N][K]) ----------------
#define TKC 16
__global__ void __launch_bounds__(256) gemm_bt(
                        const float* __restrict__ A, int lda,
                        const float* __restrict__ Bw, int ldb,
                        float* __restrict__ C, int ldc,
                        int N, int Klen,
                        const float* __restrict__ bias0,
                        int tanhA)
{
    __shared__ float As[TKC][68];
    __shared__ __align__(16) float Bs[TKC][34];

    const int tid = threadIdx.x;
    const int tx = tid & 15;
    const int ty = tid >> 4;
    const int row0 = blockIdx.y * 64;
    const int n0 = blockIdx.x * 32;

    float acc[4][2] = {};

    const int la_m = tid >> 2;
    const int la_k = (tid & 3) * 4;
    const int lb_n = tid >> 3;
    const int lb_k = (tid & 7) * 2;

    const float* Ab = A + (long)(row0 + la_m) * lda + la_k;
    const bool bvalid = (n0 + lb_n) < N;
    const float* Bb = Bw + (long)(n0 + lb_n) * ldb + lb_k;

    float a0 = Ab[0], a1 = Ab[1], a2 = Ab[2], a3 = Ab[3];
    float b0 = 0.f, b1 = 0.f;
    if (bvalid) { b0 = Bb[0]; b1 = Bb[1]; }

    for (int k0 = 0; k0 < Klen; k0 += TKC) {
        float sa0 = a0, sa1 = a1, sa2 = a2, sa3 = a3;
        if (tanhA) { sa0 = tanhfast(sa0); sa1 = tanhfast(sa1);
                     sa2 = tanhfast(sa2); sa3 = tanhfast(sa3); }
        __syncthreads();
        As[la_k + 0][la_m] = sa0; As[la_k + 1][la_m] = sa1;
        As[la_k + 2][la_m] = sa2; As[la_k + 3][la_m] = sa3;
        Bs[lb_k][lb_n] = b0; Bs[lb_k + 1][lb_n] = b1;
        __syncthreads();
        if (k0 + TKC < Klen) {
            a0 = Ab[k0 + TKC + 0]; a1 = Ab[k0 + TKC + 1];
            a2 = Ab[k0 + TKC + 2]; a3 = Ab[k0 + TKC + 3];
            if (bvalid) { b0 = Bb[k0 + TKC]; b1 = Bb[k0 + TKC + 1]; }
        }
        #pragma unroll
        for (int kk = 0; kk < TKC; kk++) {
            float4 av = *(const float4*)&As[kk][ty * 4];
            float2 bv = *(const float2*)&Bs[kk][tx * 2];
            acc[0][0] += av.x * bv.x; acc[0][1] += av.x * bv.y;
            acc[1][0] += av.y * bv.x; acc[1][1] += av.y * bv.y;
            acc[2][0] += av.z * bv.x; acc[2][1] += av.z * bv.y;
            acc[3][0] += av.w * bv.x; acc[3][1] += av.w * bv.y;
        }
    }
    #pragma unroll
    for (int i = 0; i < 4; i++) {
        int m = row0 + ty * 4 + i;
        #pragma unroll
        for (int j = 0; j < 2; j++) {
            int n = n0 + tx * 2 + j;
            if (n < N) {
                float v = acc[i][j];
                if (bias0) v += bias0[n];
                C[(long)m * ldc + n] = v;
            }
        }
    }
}

// ---------------- init: permute weights + init state ----------------
__global__ void __launch_bounds__(256) init_kernel(
                            const float* __restrict__ h0in,
                            const float* __restrict__ Wih0,
                            const float* __restrict__ Whh0,
                            const float* __restrict__ bih0,
                            const float* __restrict__ bhh0,
                            const float* __restrict__ Wih1,
                            const float* __restrict__ Whh1,
                            const float* __restrict__ bih1,
                            const float* __restrict__ bhh1,
                            const float* __restrict__ Wif)
{
    int i = blockIdx.x * 256 + threadIdx.x;
    if (i < BB * MM * MM) g_link[i] = 0.f;
    if (i < BB * MM * WWD) g_mem[i] = DELTA;
    if (i < G4H * 1024) {
        int n = i >> 10, k = i & 1023;
        int h = n >> 2, g = n & 3;
        g_W1p[i] = (k < 512) ? Wih1[(g * 512 + h) * 512 + k]
                             : Whh1[(g * 512 + h) * 512 + (k - 512)];
    }
    if (i < G4H * 512) {
        int n = i >> 9, k = i & 511;
        int h = n >> 2, g = n & 3;
        g_W0p[i] = Whh0[(g * 512 + h) * 512 + k];
    }
    if (i < G4H * 256) {
        int n = i >> 8, k = i & 255;
        int h = n >> 2, g = n & 3;
        g_Wih0p[i] = Wih0[(g * 512 + h) * 512 + k];
    }
    if (i < 512 * 480) {
        int k = i / 480, ii = i - k * 480;
        g_WifT[i] = (ii < IFACE) ? Wif[ii * 512 + k] : 0.f;
    }
    if (i < G4H) {
        int h = i >> 2, g = i & 3;
        g_bp0[i] = bih0[g * 512 + h] + bhh0[g * 512 + h];
        g_bp1[i] = bih1[g * 512 + h] + bhh1[g * 512 + h];
    }
    if (i < BB * HH) {
        g_h0buf[i] = h0in[i];
        g_c0[i] = h0in[i];
        g_c1[i] = h0in[32768 + i];
    }
    if (i < BB * 1024) {
        int b = i >> 10, c = i & 1023;
        if (c >= 512) g_in1[i] = h0in[32768 + b * 512 + (c - 512)];
    }
    if (i < BB * RR * MM) g_rw[i] = DELTA;
    if (i < BB * MM) { g_ww[i] = DELTA; g_usage[i] = 0.f; g_prec[i] = 0.f; }
}

// ---------------- kernel A: lstm0 (blocks 0..127) + lstm1 h1-half partial
//                  (blocks 128..255). Both K=512, R10-proven tile/pipeline. ----
__global__ void __launch_bounds__(256) stageA_kernel(
                             int t, const float* __restrict__ h0prev,
                             float* __restrict__ h0next, float* __restrict__ in1cur)
{
    __shared__ float As[32][65];
    __shared__ __align__(16) float Bs[32][20];
    const int tid = threadIdx.x;
    const int r = tid & 63, q = tid >> 6;
    const int bx = blockIdx.x;
    const int part = (bx >= 128);
    const int nb = part ? (bx - 128) : bx;
    const int n0 = nb * 16;
    const int a_row = tid >> 2, a_kb = (tid & 3) * 8;
    const int b_n = tid >> 4, b_k2 = (tid & 15) * 2;

    // lstm0: A = h0prev (lda 512), B = W0p (ldb 512)
    // partial: A = in1cur + 512 (h1_old, lda 1024), B = W1p + 512 (ldb 1024)
    const float* Ap = part ? (in1cur + 512 + a_row * 1024 + a_kb)
                           : (h0prev + a_row * 512 + a_kb);
    const float* Bp = part ? (g_W1p + (n0 + b_n) * 1024 + 512 + b_k2)
                           : (g_W0p + (n0 + b_n) * 512 + b_k2);
    float acc0 = 0.f, acc1 = 0.f, acc2 = 0.f, acc3 = 0.f;

    float4 ra0 = *(const float4*)(Ap);
    float4 ra1 = *(const float4*)(Ap + 4);
    float rb0 = Bp[0], rb1 = Bp[1];

    #pragma unroll 1
    for (int k0 = 0; k0 < 512; k0 += 32) {
        __syncthreads();
        As[a_kb + 0][a_row] = ra0.x; As[a_kb + 1][a_row] = ra0.y;
        As[a_kb + 2][a_row] = ra0.z; As[a_kb + 3][a_row] = ra0.w;
        As[a_kb + 4][a_row] = ra1.x; As[a_kb + 5][a_row] = ra1.y;
        As[a_kb + 6][a_row] = ra1.z; As[a_kb + 7][a_row] = ra1.w;
        Bs[b_k2][b_n] = rb0; Bs[b_k2 + 1][b_n] = rb1;
        __syncthreads();
        if (k0 + 32 < 512) {
            ra0 = *(const float4*)(Ap + k0 + 32);
            ra1 = *(const float4*)(Ap + k0 + 36);
            rb0 = Bp[k0 + 32]; rb1 = Bp[k0 + 33];
        }
        #pragma unroll
        for (int kk = 0; kk < 32; kk++) {
            float a = As[kk][r];
            float4 b4 = *(const float4*)&Bs[kk][q * 4];
            acc0 += a * b4.x; acc1 += a * b4.y; acc2 += a * b4.z; acc3 += a * b4.w;
        }
    }
    int h = nb * 4 + q;
    if (part) {
        float4 v; v.x = acc0; v.y = acc1; v.z = acc2; v.w = acc3;
        *(float4*)&g_p1h[r * 2048 + h * 4] = v;
    } else {
        float4 xp = *(const float4*)&g_xprojp[((long)(r * TT + t)) * G4H + h * 4];
        float gi = acc0 + xp.x, gf = acc1 + xp.y, gg = acc2 + xp.z, go = acc3 + xp.w;
        float c = sigf(gf) * g_c0[r * 512 + h] + sigf(gi) * tanhfast(gg);
        g_c0[r * 512 + h] = c;
        float hh = sigf(go) * tanhfast(c);
        h0next[r * 512 + h] = hh;
        in1cur[r * 1024 + h] = hh;
    }
}

// ---------------- lstm1': K=512 over h0(t), adds g_p1h partial ----------------
__global__ void __launch_bounds__(256) lstm1_kernel(
                             int t, const float* __restrict__ A,
                             float* __restrict__ in1next)
{
    __shared__ float As[32][65];
    __shared__ __align__(16) float Bs[32][20];
    const int tid = threadIdx.x;
    const int r = tid & 63, q = tid >> 6;
    const int n0 = blockIdx.x * 16;
    const int a_row = tid >> 2, a_kb = (tid & 3) * 8;
    const int b_n = tid >> 4, b_k2 = (tid & 15) * 2;
    const float* Ap = A + a_row * 1024 + a_kb;            // h0(t) half
    const float* Bp = g_W1p + (n0 + b_n) * 1024 + b_k2;   // first 512 cols
    float acc0 = 0.f, acc1 = 0.f, acc2 = 0.f, acc3 = 0.f;

    float4 ra0 = *(const float4*)(Ap);
    float4 ra1 = *(const float4*)(Ap + 4);
    float rb0 = Bp[0], rb1 = Bp[1];

    #pragma unroll 1
    for (int k0 = 0; k0 < 512; k0 += 32) {
        __syncthreads();
        As[a_kb + 0][a_row] = ra0.x; As[a_kb + 1][a_row] = ra0.y;
        As[a_kb + 2][a_row] = ra0.z; As[a_kb + 3][a_row] = ra0.w;
        As[a_kb + 4][a_row] = ra1.x; As[a_kb + 5][a_row] = ra1.y;
        As[a_kb + 6][a_row] = ra1.z; As[a_kb + 7][a_row] = ra1.w;
        Bs[b_k2][b_n] = rb0; Bs[b_k2 + 1][b_n] = rb1;
        __syncthreads();
        if (k0 + 32 < 512) {
            ra0 = *(const float4*)(Ap + k0 + 32);
            ra1 = *(const float4*)(Ap + k0 + 36);
            rb0 = Bp[k0 + 32]; rb1 = Bp[k0 + 33];
        }
        #pragma unroll
        for (int kk = 0; kk < 32; kk++) {
            float a = As[kk][r];
            float4 b4 = *(const float4*)&Bs[kk][q * 4];
            acc0 += a * b4.x; acc1 += a * b4.y; acc2 += a * b4.z; acc3 += a * b4.w;
        }
    }
    int h = blockIdx.x * 4 + q;
    float4 bi = *(const float4*)&g_bp1[h * 4];
    float4 pp = *(const float4*)&g_p1h[r * 2048 + h * 4];
    float gi = acc0 + pp.x + bi.x, gf = acc1 + pp.y + bi.y;
    float gg = acc2 + pp.z + bi.z, go = acc3 + pp.w + bi.w;
    float c = sigf(gf) * g_c1[r * 512 + h] + sigf(gi) * tanhfast(gg);
    g_c1[r * 512 + h] = c;
    float h1 = sigf(go) * tanhfast(c);
    in1next[r * 1024 + 512 + h] = h1;
    float o = fminf(fmaxf(h1, -CLIPV), CLIPV);
    g_outb[r * 512 + h] = o;
    g_ys[((long)(r * TT + t)) * NNOUT + h] = o;
}

// ---------------- memory step: one block (512 thr) per batch ----------------
// Now also computes xi = Wif @ outb[b] + bif in-kernel (coalesced over WifT).
#define MEM_SMEM_FLOATS (256*65 + 4*1024 + 6*256 + 256 + 480 + 512 + 16 + 96 + 512)

__device__ __forceinline__ float red512_max(float v, float* s_scr, int tid) {
    #pragma unroll
    for (int o = 16; o > 0; o >>= 1) v = fmaxf(v, __shfl_xor_sync(0xffffffffu, v, o));
    if ((tid & 31) == 0) s_scr[tid >> 5] = v;
    __syncthreads();
    if (tid < 32) {
        float x = (tid < 16) ? s_scr[tid] : -1e30f;
        #pragma unroll
        for (int o = 8; o > 0; o >>= 1) x = fmaxf(x, __shfl_xor_sync(0xffffffffu, x, o));
        if (tid == 0) s_scr[0] = x;
    }
    __syncthreads();
    float rr = s_scr[0];
    __syncthreads();
    return rr;
}
__device__ __forceinline__ float red512_sum(float v, float* s_scr, int tid) {
    #pragma unroll
    for (int o = 16; o > 0; o >>= 1) v += __shfl_xor_sync(0xffffffffu, v, o);
    if ((tid & 31) == 0) s_scr[tid >> 5] = v;
    __syncthreads();
    if (tid < 32) {
        float x = (tid < 16) ? s_scr[tid] : 0.f;
        #pragma unroll
        for (int o = 8; o > 0; o >>= 1) x += __shfl_xor_sync(0xffffffffu, x, o);
        if (tid == 0) s_scr[0] = x;
    }
    __syncthreads();
    float rr = s_scr[0];
    __syncthreads();
    return rr;
}

__global__ void __launch_bounds__(512) mem_kernel(int t, const float* __restrict__ bif)
{
    extern __shared__ float sm[];
    float* s_mem  = sm;                     // 256*65
    float* s_rwo  = s_mem + 256 * 65;       // 1024
    float* s_rwn  = s_rwo + 1024;           // 1024
    float* s_fwd  = s_rwn + 1024;           // 1024
    float* s_bwd  = s_fwd + 1024;           // 1024
    float* s_ww   = s_bwd + 1024;           // 256
    float* s_wwo  = s_ww + 256;
    float* s_prec = s_wwo + 256;
    float* s_alloc= s_prec + 256;
    float* s_wcw  = s_alloc + 256;
    float* s_key  = s_wcw + 256;
    int*   s_idx  = (int*)(s_key + 256);    // 256
    float* s_xi   = (float*)(s_idx + 256);  // 480
    float* s_red  = s_xi + 480;             // 512
    float* s_rm   = s_red + 512;            // 16
    float* s_scr  = s_rm + 16;              // 96
    float* s_h    = s_scr + 96;             // 512 (controller output)

    const int tid = threadIdx.x;
    const int b = blockIdx.x;
    const int m = tid & 255;
    const int warp = tid >> 5, lane = tid & 31;

    // ---- load controller output, compute xi = WifT^T h + bif, activations ----
    s_h[tid] = g_outb[b * 512 + tid];
    for (int i = tid; i < 1024; i += 512) s_rwo[i] = g_rw[b * 1024 + i];
    if (tid < 256) {
        s_wwo[tid]  = g_ww[b * 256 + tid];
        s_prec[tid] = g_prec[b * 256 + tid];
    }
    for (int i = tid; i < MM * WWD; i += 512)
        s_mem[(i >> 6) * 65 + (i & 63)] = g_mem[(long)b * MM * WWD + i];
    __syncthreads();

    if (tid < IFACE) {
        float acc = bif[tid];
        const float* wp = g_WifT + tid;
        #pragma unroll 8
        for (int k = 0; k < 512; k++)
            acc += wp[k * 480] * s_h[k];
        float v = acc;
        int i = tid;
        if      (i < 256) v = tanhfast(v);
        else if (i < 260) v = splusf(v);
        else if (i < 324) v = tanhfast(v);
        else if (i == 324) v = splusf(v);
        else if (i < 389) v = sigf(v);
        else if (i < 453) v = tanhfast(v);
        else if (i < 459) v = sigf(v);
        s_xi[i] = v;
    }
    __syncthreads();

    if (tid < 4) {
        float a = s_xi[459 + tid * 3], bb2 = s_xi[460 + tid * 3], cc = s_xi[461 + tid * 3];
        float mx = fmaxf(a, fmaxf(bb2, cc));
        float ea = __expf(a - mx), eb = __expf(bb2 - mx), ec = __expf(cc - mx);
        float s = ea + eb + ec;
        s_rm[tid * 3] = __fdividef(ea, s);
        s_rm[tid * 3 + 1] = __fdividef(eb, s);
        s_rm[tid * 3 + 2] = __fdividef(ec, s);
    }

    // ---- usage update (old ww, old rw) ----
    float u = 0.f;
    if (tid < 256) {
        u = g_usage[b * 256 + m];
        u = u + (1.f - u) * s_wwo[m];
        float psi = 1.f;
        #pragma unroll
        for (int r = 0; r < 4; r++) psi *= 1.f - s_xi[453 + r] * s_rwo[r * 256 + m];
        u *= psi;
        g_usage[b * 256 + m] = u;
    }

    // ---- write content weights (OLD memory) ----
    float z = -1e30f;
    if (tid < 256) {
        float nk = 0.f, nm = 0.f, dot = 0.f;
        #pragma unroll 8
        for (int w = 0; w < 64; w++) {
            float kv = s_xi[260 + w];
            float mv = s_mem[m * 65 + w];
            nk += kv * kv; nm += mv * mv; dot += mv * kv;
        }
        nk = sqrtf(nk) + DELTA; nm = sqrtf(nm) + DELTA;
        z = __fdividef(dot, nm * nk) * s_xi[324];
    }
    float mx = red512_max(z, s_scr, tid);
    float e = (tid < 256) ? __expf(z - mx) : 0.f;
    float ssum = red512_sum(e, s_scr, tid);
    if (tid < 256) s_wcw[m] = __fdividef(e, ssum);

    // ---- allocation: stable ascending bitonic sort of u' ----
    if (tid < 256) { s_key[m] = DELTA + (1.f - DELTA) * u; s_idx[m] = m; }
    __syncthreads();
    for (int k = 2; k <= 256; k <<= 1) {
        for (int j = k >> 1; j > 0; j >>= 1) {
            if (tid < 256) {
                int l = tid ^ j;
                if (l > tid) {
                    bool up = ((tid & k) == 0);
                    float ki = s_key[tid], kl = s_key[l];
                    int ii = s_idx[tid], il = s_idx[l];
                    bool igt = (ki > kl) || (ki == kl && ii > il);
                    if (igt == up) { s_key[tid] = kl; s_key[l] = ki; s_idx[tid] = il; s_idx[l] = ii; }
                }
            }
            __syncthreads();
        }
    }
    if (tid < 256) s_red[tid] = s_key[tid];
    __syncthreads();
    for (int off = 1; off < 256; off <<= 1) {
        float prev = 1.f;
        if (tid < 256 && tid >= off) prev = s_red[tid - off];
        __syncthreads();
        if (tid < 256) s_red[tid] *= prev;
        __syncthreads();
    }
    if (tid < 256) {
        float excl = (tid == 0) ? 1.f : s_red[tid - 1];
        s_alloc[s_idx[tid]] = (1.f - s_key[tid]) * excl;
    }
    __syncthreads();

    // ---- new write weights ----
    float wwn = 0.f;
    if (tid < 256) {
        float ag = s_xi[457], wg = s_xi[458];
        wwn = wg * (ag * s_alloc[m] + (1.f - ag) * s_wcw[m]);
        s_ww[m] = wwn;
    }
    float sumww = red512_sum(wwn, s_scr, tid);

    // ---- memory erase + write ----
    {
        int mm2 = tid >> 1, w0 = (tid & 1) * 32;
        float wv = s_ww[mm2];
        #pragma unroll 8
        for (int w = 0; w < 32; w++) {
            int idx = mm2 * 65 + w0 + w;
            s_mem[idx] = s_mem[idx] * (1.f - wv * s_xi[325 + w0 + w]) + wv * s_xi[389 + w0 + w];
        }
    }
    __syncthreads();
    for (int i = tid; i < MM * WWD; i += 512)
        g_mem[(long)b * MM * WWD + i] = s_mem[(i >> 6) * 65 + (i & 63)];

    // ---- link row pass: update + fwd (16 warps x 16 rows) ----
    float* lrow = g_link + (long)b * MM * MM;
    for (int ii = 0; ii < 16; ii++) {
        int i = warp * 16 + ii;
        float wwi = s_ww[i];
        float ps = 1.f - wwi;
        float f0 = 0.f, f1 = 0.f, f2 = 0.f, f3 = 0.f;
        #pragma unroll
        for (int it = 0; it < 2; it++) {
            int j0 = (it * 32 + lane) * 4;
            float4 lo = *(float4*)&lrow[i * 256 + j0];
            float4 wj = *(float4*)&s_ww[j0];
            float4 pj = *(float4*)&s_prec[j0];
            float4 ln;
            ln.x = (ps - wj.x) * lo.x + wwi * pj.x;
            ln.y = (ps - wj.y) * lo.y + wwi * pj.y;
            ln.z = (ps - wj.z) * lo.z + wwi * pj.z;
            ln.w = (ps - wj.w) * lo.w + wwi * pj.w;
            if (j0 + 0 == i) ln.x = 0.f;
            if (j0 + 1 == i) ln.y = 0.f;
            if (j0 + 2 == i) ln.z = 0.f;
            if (j0 + 3 == i) ln.w = 0.f;
            *(float4*)&lrow[i * 256 + j0] = ln;
            float4 r0v = *(float4*)&s_rwo[j0];
            float4 r1v = *(float4*)&s_rwo[256 + j0];
            float4 r2v = *(float4*)&s_rwo[512 + j0];
            float4 r3v = *(float4*)&s_rwo[768 + j0];
            f0 += ln.x * r0v.x + ln.y * r0v.y + ln.z * r0v.z + ln.w * r0v.w;
            f1 += ln.x * r1v.x + ln.y * r1v.y + ln.z * r1v.z + ln.w * r1v.w;
            f2 += ln.x * r2v.x + ln.y * r2v.y + ln.z * r2v.z + ln.w * r2v.w;
            f3 += ln.x * r3v.x + ln.y * r3v.y + ln.z * r3v.z + ln.w * r3v.w;
        }
        #pragma unroll
        for (int o = 16; o > 0; o >>= 1) {
            f0 += __shfl_xor_sync(0xffffffffu, f0, o);
            f1 += __shfl_xor_sync(0xffffffffu, f1, o);
            f2 += __shfl_xor_sync(0xffffffffu, f2, o);
            f3 += __shfl_xor_sync(0xffffffffu, f3, o);
        }
        if (lane == 0) {
            s_fwd[i] = f0; s_fwd[256 + i] = f1; s_fwd[512 + i] = f2; s_fwd[768 + i] = f3;
        }
    }
    __syncthreads();

    // ---- bwd column pass over NEW link (two-phase smem combine, no atomics) ----
    {
        int jb = (warp & 7) * 32 + lane;
        int ibase = (warp >> 3) * 128;
        float b0 = 0.f, b1 = 0.f, b2 = 0.f, b3 = 0.f;
        #pragma unroll 4
        for (int i = 0; i < 128; i++) {
            float lv = lrow[(ibase + i) * 256 + jb];
            b0 += s_rwo[ibase + i] * lv;
            b1 += s_rwo[256 + ibase + i] * lv;
            b2 += s_rwo[512 + ibase + i] * lv;
            b3 += s_rwo[768 + ibase + i] * lv;
        }
        if (warp < 8) {
            s_bwd[jb] = b0; s_bwd[256 + jb] = b1; s_bwd[512 + jb] = b2; s_bwd[768 + jb] = b3;
        }
        __syncthreads();
        if (warp >= 8) {
            s_bwd[jb] += b0; s_bwd[256 + jb] += b1; s_bwd[512 + jb] += b2; s_bwd[768 + jb] += b3;
        }
        __syncthreads();
    }

    // ---- precedence + ww stores ----
    if (tid < 256) {
        g_prec[b * 256 + m] = (1.f - sumww) * s_prec[m] + s_ww[m];
        g_ww[b * 256 + m] = s_ww[m];
    }

    // ---- read content weights (NEW memory), 4 heads in parallel ----
    const int r0 = tid >> 8;
    float nk0 = 0.f, nk1 = 0.f;
    #pragma unroll 8
    for (int w = 0; w < 64; w++) {
        float k0v = s_xi[r0 * 64 + w], k1v = s_xi[(r0 + 2) * 64 + w];
        nk0 += k0v * k0v; nk1 += k1v * k1v;
    }
    nk0 = sqrtf(nk0) + DELTA; nk1 = sqrtf(nk1) + DELTA;
    float nm2 = 0.f, d0 = 0.f, d1 = 0.f;
    #pragma unroll 8
    for (int w = 0; w < 64; w++) {
        float mv = s_mem[m * 65 + w];
        nm2 += mv * mv;
        d0 += mv * s_xi[r0 * 64 + w];
        d1 += mv * s_xi[(r0 + 2) * 64 + w];
    }
    nm2 = sqrtf(nm2) + DELTA;
    float z0 = __fdividef(d0, nm2 * nk0) * s_xi[256 + r0];
    float z1 = __fdividef(d1, nm2 * nk1) * s_xi[256 + r0 + 2];

    {
        float w0 = z0, w1 = z1;
        #pragma unroll
        for (int o = 16; o > 0; o >>= 1) {
            w0 = fmaxf(w0, __shfl_xor_sync(0xffffffffu, w0, o));
            w1 = fmaxf(w1, __shfl_xor_sync(0xffffffffu, w1, o));
        }
        if (lane == 0) { s_scr[warp] = w0; s_scr[16 + warp] = w1; }
    }
    __syncthreads();
    if (tid < 32) {
        float v = s_scr[tid];
        v = fmaxf(v, __shfl_xor_sync(0xffffffffu, v, 4, 8));
        v = fmaxf(v, __shfl_xor_sync(0xffffffffu, v, 2, 8));
        v = fmaxf(v, __shfl_xor_sync(0xffffffffu, v, 1, 8));
        if ((tid & 7) == 0) s_scr[32 + (tid >> 3)] = v;
    }
    __syncthreads();
    float e0 = __expf(z0 - s_scr[32 + r0]);
    float e1 = __expf(z1 - s_scr[34 + r0]);
    {
        float w0 = e0, w1 = e1;
        #pragma unroll
        for (int o = 16; o > 0; o >>= 1) {
            w0 += __shfl_xor_sync(0xffffffffu, w0, o);
            w1 += __shfl_xor_sync(0xffffffffu, w1, o);
        }
        if (lane == 0) { s_scr[40 + warp] = w0; s_scr[56 + warp] = w1; }
    }
    __syncthreads();
    if (tid < 32) {
        float v = s_scr[40 + tid];
        v += __shfl_xor_sync(0xffffffffu, v, 4, 8);
        v += __shfl_xor_sync(0xffffffffu, v, 2, 8);
        v += __shfl_xor_sync(0xffffffffu, v, 1, 8);
        if ((tid & 7) == 0) s_scr[72 + (tid >> 3)] = v;
    }
    __syncthreads();
    float rc0 = __fdividef(e0, s_scr[72 + r0]);
    float rc1 = __fdividef(e1, s_scr[74 + r0]);

    // ---- new read weights ----
    {
        int rA = r0, rB = r0 + 2;
        float rnA = s_rm[rA * 3] * s_bwd[rA * 256 + m]
                  + s_rm[rA * 3 + 1] * s_fwd[rA * 256 + m]
                  + s_rm[rA * 3 + 2] * rc0;
        float rnB = s_rm[rB * 3] * s_bwd[rB * 256 + m]
                  + s_rm[rB * 3 + 1] * s_fwd[rB * 256 + m]
                  + s_rm[rB * 3 + 2] * rc1;
        s_rwn[rA * 256 + m] = rnA;
        s_rwn[rB * 256 + m] = rnB;
        g_rw[b * 1024 + rA * 256 + m] = rnA;
        g_rw[b * 1024 + rB * 256 + m] = rnB;
    }
    __syncthreads();

    // ---- read vectors (2 threads per output element) ----
    {
        int o = tid & 255, half = tid >> 8;
        int r = o >> 6, w = o & 63;
        float acc = 0.f;
        int mstart = half * 128;
        #pragma unroll 4
        for (int mm2 = mstart; mm2 < mstart + 128; mm2++)
            acc += s_rwn[r * 256 + mm2] * s_mem[mm2 * 65 + w];
        s_red[tid] = acc;
    }
    __syncthreads();
    if (tid < 256)
        g_ys[((long)(b * TT + t)) * NNOUT + 512 + tid] = s_red[tid] + s_red[tid + 256];
}

// ---------------- host orchestration ----------------
extern "C" void kernel_launch(void* const* d_in, const int* in_sizes, int n_in,
                              void* d_out, int out_size)
{
    const float* x    = (const float*)d_in[0];
    const float* h0   = (const float*)d_in[1];
    const float* Wih0 = (const float*)d_in[2];
    const float* Whh0 = (const float*)d_in[3];
    const float* bih0 = (const float*)d_in[4];
    const float* bhh0 = (const float*)d_in[5];
    const float* Wih1 = (const float*)d_in[6];
    const float* Whh1 = (const float*)d_in[7];
    const float* bih1 = (const float*)d_in[8];
    const float* bhh1 = (const float*)d_in[9];
    const float* Wif  = (const float*)d_in[10];
    const float* bif  = (const float*)d_in[11];
    const float* Wout = (const float*)d_in[12];
    const float* bout = (const float*)d_in[13];
    float* out = (float*)d_out;
    (void)in_sizes; (void)n_in; (void)out_size;

    (void)cudaFuncSetAttribute(mem_kernel, cudaFuncAttributeMaxDynamicSharedMemorySize,
                               MEM_SMEM_FLOATS * 4);

    float *p_h0, *p_in1, *p_ys, *p_Wih0p, *p_bp0, *p_xprojp;
    cudaGetSymbolAddress((void**)&p_xprojp, g_xprojp);
    cudaGetSymbolAddress((void**)&p_h0, g_h0buf);
    cudaGetSymbolAddress((void**)&p_in1, g_in1);
    cudaGetSymbolAddress((void**)&p_ys, g_ys);
    cudaGetSymbolAddress((void**)&p_Wih0p, g_Wih0p);
    cudaGetSymbolAddress((void**)&p_bp0, g_bp0);

    init_kernel<<<16384, 256>>>(h0, Wih0, Whh0, bih0, bhh0,
                                Wih1, Whh1, bih1, bhh1, Wif);

    // xprojp: (B*T,256) @ Wih0p^T + bp0 -> [b*T+t][4h+g]
    gemm_bt<<<dim3(G4H / 32, (BB * TT) / 64, 1), 256>>>(
        x, 256, p_Wih0p, 256, p_xprojp, G4H, G4H, 256, p_bp0, 0);

    for (int t = 0; t < TT; t++) {
        int p = t & 1;
        stageA_kernel<<<256, 256>>>(t, p_h0 + p * (BB * HH),
                                    p_h0 + (p ^ 1) * (BB * HH),
                                    p_in1 + p * (BB * 1024));
        lstm1_kernel<<<128, 256>>>(t, p_in1 + p * (BB * 1024),
                                   p_in1 + (p ^ 1) * (BB * 1024));
        mem_kernel<<<BB, 512, MEM_SMEM_FLOATS * 4>>>(t, bif);
    }

    // final: out = tanh(ys) @ Wout^T + bout (tanh folded into A-load)
    gemm_bt<<<dim3(256 / 32, (BB * TT) / 64, 1), 256>>>(
        p_ys, NNOUT, Wout, NNOUT, out, 256, 256, NNOUT, bout, 1);
}